// round 10
// baseline (speedup 1.0000x reference)
#include <cuda_runtime.h>
#include <cuda_bf16.h>
#include <cstdint>

// ---------------------------------------------------------------------------
// SpikingSelfAttention, compute_100-safe (HMMA mma.sync, no tcgen05).
//   QKV:  3-product 2-way bf16-split HMMA (x1w1 + x1w2 + x2w1),
//         pre-act error ~8e-6 (max ~5e-5)
//   LIF:  flags elements with any |mem-1| < 2e-4 (borderline spike decisions)
//   FIX:  flagged elements recomputed with bit-exact serial fp32 fmaf chains
//         (k-ascending, bit-identical to reference; proven rounds 2 & 7)
//   proj: o = q_spike*ctx is exact integer 0..4 -> 2-product HMMA (Wp split)
// ---------------------------------------------------------------------------

namespace {
constexpr int    kT    = 4;
constexpr int    kM    = 16384;               // B*N
constexpr int    kD    = 512;
constexpr int    kRows = kT * kM;             // 65536
constexpr size_t kMD   = (size_t)kM * kD;     // 8388608
constexpr size_t kTMD  = (size_t)kRows * kD;  // 33554432
constexpr int    kWEl  = kD * kD;             // 262144

constexpr int BM = 128, BN = 128, KC = 64;
constexpr int LDS_H  = 72;                    // padded halves per smem row
constexpr int TILE_H = BM * LDS_H;
constexpr int BUF_H  = 2 * TILE_H;
constexpr size_t SMEM_BYTES = 2 * (size_t)BUF_H * 2;   // 73728

constexpr float  kDelta = 2e-4f;              // borderline flag margin
constexpr int    kFlagCap = 1 << 21;          // 2M flag slots (expect ~1e4)
}

// Scratch (__device__ globals; allocation-free rule)
__device__ float         g_pre[3 * kTMD];     // q,k,v pre-activations (fp32)
__device__ __nv_bfloat16 g_as[2 * kTMD];      // x splits x1,x2
__device__ __nv_bfloat16 g_o[kTMD];           // q_spike*context (exact bf16)
__device__ __nv_bfloat16 g_ws[8 * kWEl];      // [w 0..3][split 0..1] weights
__device__ int           g_cnt;               // flagged-element count
__device__ int           g_flags[kFlagCap];   // flat (i*kD+d) indices

// ------------------------------- helpers -----------------------------------
__device__ __forceinline__ uint32_t smem_u32(const void* p) {
    uint32_t a;
    asm("{ .reg .u64 t; cvta.to.shared.u64 t, %1; cvt.u32.u64 %0, t; }" : "=r"(a) : "l"(p));
    return a;
}
#define CP16(dst, src) \
    asm volatile("cp.async.cg.shared.global [%0], [%1], 16;" :: "r"(dst), "l"(src) : "memory")
#define CP_COMMIT() asm volatile("cp.async.commit_group;" ::: "memory")
#define CP_WAIT1()  asm volatile("cp.async.wait_group 1;" ::: "memory")
#define CP_WAIT0()  asm volatile("cp.async.wait_group 0;" ::: "memory")

__device__ __forceinline__ uint32_t ld32(const __nv_bfloat16* p) {
    return *reinterpret_cast<const uint32_t*>(p);
}
__device__ __forceinline__ void mma16816(float* c, const uint32_t* a, const uint32_t* b) {
    asm volatile(
        "mma.sync.aligned.m16n8k16.row.col.f32.bf16.bf16.f32 "
        "{%0,%1,%2,%3}, {%4,%5,%6,%7}, {%8,%9}, {%0,%1,%2,%3};"
        : "+f"(c[0]), "+f"(c[1]), "+f"(c[2]), "+f"(c[3])
        : "r"(a[0]), "r"(a[1]), "r"(a[2]), "r"(a[3]), "r"(b[0]), "r"(b[1]));
}

// --------------------------- HMMA GEMM core --------------------------------
// C[BM x BN] tile at (ybase, jbase):  C = sum_p A_p * W_p^T  (+ bias)
template <int NPROD, bool BIAS>
__device__ __forceinline__ void gemm_hmma(const __nv_bfloat16* const (&Ap)[NPROD],
                                          const __nv_bfloat16* const (&Wp)[NPROD],
                                          float* __restrict__ C,
                                          const float* __restrict__ bias,
                                          int ybase, int jbase) {
    extern __shared__ __nv_bfloat16 sm[];
    const int tid = threadIdx.x, lane = tid & 31, wid = tid >> 5;
    const int wr = wid & 3, wc = wid >> 2;     // warp grid 4(m) x 2(n)

    float acc[2][8][4];
#pragma unroll
    for (int mt = 0; mt < 2; mt++)
#pragma unroll
        for (int nt = 0; nt < 8; nt++)
#pragma unroll
            for (int e = 0; e < 4; e++) acc[mt][nt][e] = 0.f;

    const int srow = tid >> 3;                 // cp.async staging map
    const int su8  = tid & 7;

    auto load_chunk = [&](int g, int buf) {
        const int p = g >> 3, c = g & 7;
        const __nv_bfloat16* As = Ap[p] + (size_t)ybase * kD + c * KC;
        const __nv_bfloat16* Ws = Wp[p] + (size_t)jbase * kD + c * KC;
        __nv_bfloat16* Ad = sm + buf * BUF_H;
        __nv_bfloat16* Bd = Ad + TILE_H;
#pragma unroll
        for (int i = 0; i < 4; i++) {
            const int row = srow + 32 * i;
            CP16(smem_u32(Ad + row * LDS_H + su8 * 8), As + (size_t)row * kD + su8 * 8);
        }
#pragma unroll
        for (int i = 0; i < 4; i++) {
            const int row = srow + 32 * i;
            CP16(smem_u32(Bd + row * LDS_H + su8 * 8), Ws + (size_t)row * kD + su8 * 8);
        }
    };

    auto compute = [&](int buf) {
        const __nv_bfloat16* Ad = sm + buf * BUF_H;
        const __nv_bfloat16* Bd = Ad + TILE_H;
        const __nv_bfloat16* aBase = Ad + (wr * 32 + (lane >> 2)) * LDS_H + (lane & 3) * 2;
        const __nv_bfloat16* bBase = Bd + (wc * 64 + (lane >> 2)) * LDS_H + (lane & 3) * 2;
#pragma unroll
        for (int k16 = 0; k16 < KC / 16; k16++) {
            uint32_t a[2][4], b[8][2];
#pragma unroll
            for (int mt = 0; mt < 2; mt++) {
                const __nv_bfloat16* pa = aBase + mt * 16 * LDS_H + k16 * 16;
                a[mt][0] = ld32(pa);
                a[mt][1] = ld32(pa + 8 * LDS_H);
                a[mt][2] = ld32(pa + 8);
                a[mt][3] = ld32(pa + 8 * LDS_H + 8);
            }
#pragma unroll
            for (int nt = 0; nt < 8; nt++) {
                const __nv_bfloat16* pb = bBase + nt * 8 * LDS_H + k16 * 16;
                b[nt][0] = ld32(pb);
                b[nt][1] = ld32(pb + 8);
            }
#pragma unroll
            for (int nt = 0; nt < 8; nt++)
#pragma unroll
                for (int mt = 0; mt < 2; mt++) mma16816(acc[mt][nt], a[mt], b[nt]);
        }
    };

    constexpr int G = NPROD * 8;
    load_chunk(0, 0);
    CP_COMMIT();
    for (int g = 0; g < G; ++g) {
        if (g + 1 < G) {
            load_chunk(g + 1, (g + 1) & 1);
            CP_COMMIT();
            CP_WAIT1();
        } else {
            CP_WAIT0();
        }
        __syncthreads();
        compute(g & 1);
        __syncthreads();
    }

#pragma unroll
    for (int mt = 0; mt < 2; mt++)
#pragma unroll
        for (int half = 0; half < 2; half++) {
            const int m = ybase + wr * 32 + mt * 16 + (lane >> 2) + half * 8;
            float* Crow = C + (size_t)m * kD + jbase + wc * 64;
#pragma unroll
            for (int nt = 0; nt < 8; nt++) {
                const int col = nt * 8 + (lane & 3) * 2;
                float2 v = {acc[mt][nt][half * 2], acc[mt][nt][half * 2 + 1]};
                if (BIAS) {
                    v.x += bias[jbase + wc * 64 + col];
                    v.y += bias[jbase + wc * 64 + col + 1];
                }
                *(float2*)(Crow + col) = v;
            }
        }
}

// grid 6144: blockIdx = mtile*12 + w*4 + ntile (A-split L2 reuse across w,nt)
__global__ __launch_bounds__(256, 2) void qkv_mma() {
    const int bx = blockIdx.x;
    const int mtile = bx / 12, sub = bx % 12, w = sub >> 2, nt = sub & 3;
    const __nv_bfloat16* w1 = g_ws + (size_t)(2 * w) * kWEl;
    const __nv_bfloat16* w2 = w1 + kWEl;
    // products: x1*w1 + x1*w2 + x2*w1
    const __nv_bfloat16* Ap[3] = {g_as, g_as, g_as + kTMD};
    const __nv_bfloat16* Wb[3] = {w1, w2, w1};
    gemm_hmma<3, false>(Ap, Wb, g_pre + (size_t)w * kTMD, nullptr, mtile * BM, nt * BN);
}

// grid 2048
__global__ __launch_bounds__(256, 2) void proj_mma(const float* __restrict__ bp,
                                                   float* __restrict__ out) {
    const int mtile = blockIdx.x >> 2, nt = blockIdx.x & 3;
    const __nv_bfloat16* wp1 = g_ws + (size_t)6 * kWEl;    // Wp splits
    const __nv_bfloat16* Ap[2] = {g_o, g_o};
    const __nv_bfloat16* Wb[2] = {wp1, wp1 + kWEl};
    gemm_hmma<2, true>(Ap, Wb, out, bp, mtile * BM, nt * BN);
}

// ------------------------------ prep kernels -------------------------------
__device__ __forceinline__ void split2(float a, __nv_bfloat16& s1, __nv_bfloat16& s2) {
    s1 = __float2bfloat16(a);
    s2 = __float2bfloat16(a - __bfloat162float(s1));
}

__global__ void reset_cnt() { if (threadIdx.x == 0) g_cnt = 0; }

__global__ void split_x(const float* __restrict__ x) {
    const size_t i4 = ((size_t)blockIdx.x * 256 + threadIdx.x) * 4;
    float4 v = *(const float4*)(x + i4);
    __nv_bfloat16 a[4], b[4];
    split2(v.x, a[0], b[0]); split2(v.y, a[1], b[1]);
    split2(v.z, a[2], b[2]); split2(v.w, a[3], b[3]);
    *(uint2*)(g_as + i4)        = *(uint2*)a;
    *(uint2*)(g_as + kTMD + i4) = *(uint2*)b;
}

__global__ void split_w(const float* __restrict__ Wq, const float* __restrict__ Wk,
                        const float* __restrict__ Wv, const float* __restrict__ Wpj) {
    const int i4 = (blockIdx.x * 256 + threadIdx.x) * 4;
    const int w = i4 >> 18, off = i4 & (kWEl - 1);
    const float* src = (w == 0) ? Wq : (w == 1) ? Wk : (w == 2) ? Wv : Wpj;
    float4 v = *(const float4*)(src + off);
    __nv_bfloat16 a[4], b[4];
    split2(v.x, a[0], b[0]); split2(v.y, a[1], b[1]);
    split2(v.z, a[2], b[2]); split2(v.w, a[3], b[3]);
    __nv_bfloat16* base = g_ws + (size_t)(2 * w) * kWEl + off;
    *(uint2*)(base)        = *(uint2*)a;
    *(uint2*)(base + kWEl) = *(uint2*)b;
}

// LIF + cumsum + q*context on approx pre-acts; flags borderline elements.
__global__ void lif_fuse() {
    const size_t i4 = ((size_t)blockIdx.x * 256 + threadIdx.x) * 4;
    float mq[4] = {0, 0, 0, 0}, mk[4] = {0, 0, 0, 0};
    float mv[4] = {0, 0, 0, 0}, cx[4] = {0, 0, 0, 0};
    bool bad[4] = {false, false, false, false};
#pragma unroll
    for (int t = 0; t < kT; t++) {
        const size_t o = (size_t)t * kMD + i4;
        float4 xq = *(const float4*)(g_pre + o);
        float4 xk = *(const float4*)(g_pre + kTMD + o);
        float4 xv = *(const float4*)(g_pre + 2 * kTMD + o);
        __nv_bfloat16 ob[4];
#pragma unroll
        for (int e = 0; e < 4; e++) {
            mq[e] = mq[e] * 0.9f + (&xq.x)[e];
            mk[e] = mk[e] * 0.9f + (&xk.x)[e];
            mv[e] = mv[e] * 0.9f + (&xv.x)[e];
            bad[e] = bad[e] | (fabsf(mq[e] - 1.0f) < kDelta)
                            | (fabsf(mk[e] - 1.0f) < kDelta)
                            | (fabsf(mv[e] - 1.0f) < kDelta);
            const float sq = (mq[e] >= 1.0f) ? 1.f : 0.f;
            const float sk = (mk[e] >= 1.0f) ? 1.f : 0.f;
            const float sv = (mv[e] >= 1.0f) ? 1.f : 0.f;
            mq[e] -= sq; mk[e] -= sk; mv[e] -= sv;
            cx[e] += sk * sv;
            ob[e] = __float2bfloat16(sq * cx[e]);   // exact (0..4)
        }
        *(uint2*)(g_o + o) = *(uint2*)ob;
    }
#pragma unroll
    for (int e = 0; e < 4; e++)
        if (bad[e]) {
            int p = atomicAdd(&g_cnt, 1);
            if (p < kFlagCap) g_flags[p] = (int)(i4 + e);
        }
}

// Exact recompute of flagged elements: serial k-ascending fp32 fmaf chains
// (bit-identical to reference GEMM), exact LIF redo overwriting g_o.
__global__ void fix_flagged(const float* __restrict__ x, const float* __restrict__ Wq,
                            const float* __restrict__ Wk, const float* __restrict__ Wv) {
    const int n = g_cnt < kFlagCap ? g_cnt : kFlagCap;
    for (int j = blockIdx.x * blockDim.x + threadIdx.x; j < n;
         j += gridDim.x * blockDim.x) {
        const int e = g_flags[j];
        const int row = e >> 9, d = e & (kD - 1);
        const float* wq = Wq + (size_t)d * kD;
        const float* wk = Wk + (size_t)d * kD;
        const float* wv = Wv + (size_t)d * kD;
        float mq = 0.f, mk = 0.f, mv = 0.f, cx = 0.f;
#pragma unroll 1
        for (int t = 0; t < kT; t++) {
            const float* xr = x + ((size_t)t * kM + row) * kD;
            float aq = 0.f, ak = 0.f, av = 0.f;
            for (int k = 0; k < kD; k++) {        // strict ascending-k chains
                const float xv_ = xr[k];
                aq = fmaf(xv_, wq[k], aq);
                ak = fmaf(xv_, wk[k], ak);
                av = fmaf(xv_, wv[k], av);
            }
            mq = mq * 0.9f + aq;
            mk = mk * 0.9f + ak;
            mv = mv * 0.9f + av;
            const float sq = (mq >= 1.0f) ? 1.f : 0.f;
            const float sk = (mk >= 1.0f) ? 1.f : 0.f;
            const float sv = (mv >= 1.0f) ? 1.f : 0.f;
            mq -= sq; mk -= sk; mv -= sv;
            cx += sk * sv;
            g_o[(size_t)t * kMD + e] = __float2bfloat16(sq * cx);
        }
    }
}

// ------------------------------ launcher -----------------------------------
extern "C" void kernel_launch(void* const* d_in, const int* in_sizes, int n_in,
                              void* d_out, int out_size) {
    const float* x   = (const float*)d_in[0];
    const float* Wq  = (const float*)d_in[1];
    const float* Wk  = (const float*)d_in[2];
    const float* Wv  = (const float*)d_in[3];
    const float* Wpj = (const float*)d_in[4];
    const float* bp  = (const float*)d_in[5];
    float* out = (float*)d_out;

    cudaFuncSetAttribute(qkv_mma, cudaFuncAttributeMaxDynamicSharedMemorySize, (int)SMEM_BYTES);
    cudaFuncSetAttribute(proj_mma, cudaFuncAttributeMaxDynamicSharedMemorySize, (int)SMEM_BYTES);

    reset_cnt<<<1, 32>>>();
    split_w<<<kWEl / 256, 256>>>(Wq, Wk, Wv, Wpj);
    split_x<<<(int)(kTMD / 1024), 256>>>(x);
    qkv_mma<<<6144, 256, SMEM_BYTES>>>();
    lif_fuse<<<(int)(kMD / 1024), 256>>>();
    fix_flagged<<<1024, 128>>>(x, Wq, Wk, Wv);
    proj_mma<<<2048, 256, SMEM_BYTES>>>(bp, out);
}

// round 12
// speedup vs baseline: 1.0598x; 1.0598x over previous
#include <cuda_runtime.h>
#include <cuda_bf16.h>
#include <cstdint>

// ---------------------------------------------------------------------------
// SpikingSelfAttention, compute_100-safe (HMMA mma.sync, no tcgen05).
//   QKV:  3-product 2-way bf16-split HMMA (x1w1 + x1w2 + x2w1)
//   LIF:  flags elements with any |mem-1| < 2e-4
//   FIX:  flagged elements recomputed bit-exactly (serial fp32 fmaf chains)
//   proj: o = q_spike*ctx exact integer -> 2-product HMMA (Wp split)
// Round 11: ldmatrix fragment loads + 3-stage cp.async pipeline (1 sync/chunk)
// ---------------------------------------------------------------------------

namespace {
constexpr int    kT    = 4;
constexpr int    kM    = 16384;               // B*N
constexpr int    kD    = 512;
constexpr int    kRows = kT * kM;             // 65536
constexpr size_t kMD   = (size_t)kM * kD;     // 8388608
constexpr size_t kTMD  = (size_t)kRows * kD;  // 33554432
constexpr int    kWEl  = kD * kD;             // 262144

constexpr int BM = 128, BN = 128, KC = 64;
constexpr int LDS_H  = 72;                    // padded halves per smem row
constexpr int TILE_H = BM * LDS_H;            // 9216
constexpr int BUF_H  = 2 * TILE_H;            // A+B per stage (halves)
constexpr int STAGES = 3;
constexpr size_t SMEM_BYTES = (size_t)STAGES * BUF_H * 2;   // 110592

constexpr float  kDelta = 2e-4f;              // borderline flag margin
constexpr int    kFlagCap = 1 << 21;
}

// Scratch (__device__ globals; allocation-free rule)
__device__ float         g_pre[3 * kTMD];     // q,k,v pre-activations (fp32)
__device__ __nv_bfloat16 g_as[2 * kTMD];      // x splits x1,x2
__device__ __nv_bfloat16 g_o[kTMD];           // q_spike*context (exact bf16)
__device__ __nv_bfloat16 g_ws[8 * kWEl];      // [w 0..3][split 0..1] weights
__device__ int           g_cnt;
__device__ int           g_flags[kFlagCap];

// ------------------------------- helpers -----------------------------------
__device__ __forceinline__ uint32_t smem_u32(const void* p) {
    uint32_t a;
    asm("{ .reg .u64 t; cvta.to.shared.u64 t, %1; cvt.u32.u64 %0, t; }" : "=r"(a) : "l"(p));
    return a;
}
#define CP16(dst, src) \
    asm volatile("cp.async.cg.shared.global [%0], [%1], 16;" :: "r"(dst), "l"(src) : "memory")
#define CP_COMMIT() asm volatile("cp.async.commit_group;" ::: "memory")
#define CP_WAIT1()  asm volatile("cp.async.wait_group 1;" ::: "memory")
#define CP_WAIT0()  asm volatile("cp.async.wait_group 0;" ::: "memory")

__device__ __forceinline__ void ldsm_x4(uint32_t& r0, uint32_t& r1,
                                        uint32_t& r2, uint32_t& r3, uint32_t addr) {
    asm volatile("ldmatrix.sync.aligned.m8n8.x4.shared.b16 {%0,%1,%2,%3}, [%4];"
                 : "=r"(r0), "=r"(r1), "=r"(r2), "=r"(r3) : "r"(addr));
}
__device__ __forceinline__ void mma16816(float* c, const uint32_t* a, const uint32_t* b) {
    asm volatile(
        "mma.sync.aligned.m16n8k16.row.col.f32.bf16.bf16.f32 "
        "{%0,%1,%2,%3}, {%4,%5,%6,%7}, {%8,%9}, {%0,%1,%2,%3};"
        : "+f"(c[0]), "+f"(c[1]), "+f"(c[2]), "+f"(c[3])
        : "r"(a[0]), "r"(a[1]), "r"(a[2]), "r"(a[3]), "r"(b[0]), "r"(b[1]));
}

// --------------------------- HMMA GEMM core --------------------------------
// C[BM x BN] tile at (ybase, jbase):  C = sum_p A_p * W_p^T  (+ bias)
template <int NPROD, bool BIAS>
__device__ __forceinline__ void gemm_hmma(const __nv_bfloat16* const (&Ap)[NPROD],
                                          const __nv_bfloat16* const (&Wp)[NPROD],
                                          float* __restrict__ C,
                                          const float* __restrict__ bias,
                                          int ybase, int jbase) {
    extern __shared__ __nv_bfloat16 sm[];
    const uint32_t smb = smem_u32(sm);
    const int tid = threadIdx.x, lane = tid & 31, wid = tid >> 5;
    const int wr = wid & 3, wc = wid >> 2;     // warp grid 4(m) x 2(n)

    float acc[2][8][4];
#pragma unroll
    for (int mt = 0; mt < 2; mt++)
#pragma unroll
        for (int nt = 0; nt < 8; nt++)
#pragma unroll
            for (int e = 0; e < 4; e++) acc[mt][nt][e] = 0.f;

    const int srow = tid >> 3;                 // cp.async staging map
    const int su8  = tid & 7;

    auto load_chunk = [&](int g, int buf) {
        const int p = g >> 3, c = g & 7;
        const __nv_bfloat16* As = Ap[p] + (size_t)ybase * kD + c * KC;
        const __nv_bfloat16* Ws = Wp[p] + (size_t)jbase * kD + c * KC;
        __nv_bfloat16* Ad = sm + buf * BUF_H;
        __nv_bfloat16* Bd = Ad + TILE_H;
#pragma unroll
        for (int i = 0; i < 4; i++) {
            const int row = srow + 32 * i;
            CP16(smem_u32(Ad + row * LDS_H + su8 * 8), As + (size_t)row * kD + su8 * 8);
        }
#pragma unroll
        for (int i = 0; i < 4; i++) {
            const int row = srow + 32 * i;
            CP16(smem_u32(Bd + row * LDS_H + su8 * 8), Ws + (size_t)row * kD + su8 * 8);
        }
    };

    // ldmatrix per-lane address components (fixed across chunks)
    const int l7 = lane & 7, sel = lane >> 3;
    // A frags a0..a3: rows (+0/+8 via sel&1), k-halves (+0/+8 via sel>>1)
    const uint32_t aOff = (uint32_t)(((wr * 32 + l7 + (sel & 1) * 8) * LDS_H
                                      + (sel >> 1) * 8) * 2);
    // B frags (pair p): n-rows (+0/+8 via sel>>1), k-halves (+0/+8 via sel&1)
    const uint32_t bOff = (uint32_t)(((wc * 64 + l7 + (sel >> 1) * 8) * LDS_H
                                      + (sel & 1) * 8) * 2 + TILE_H * 2);

    auto compute = [&](int buf) {
        const uint32_t base = smb + (uint32_t)(buf * BUF_H * 2);
        const uint32_t aB = base + aOff;
        const uint32_t bB = base + bOff;
#pragma unroll
        for (int k16 = 0; k16 < KC / 16; k16++) {
            uint32_t a[2][4], b[8][2];
#pragma unroll
            for (int mt = 0; mt < 2; mt++)
                ldsm_x4(a[mt][0], a[mt][1], a[mt][2], a[mt][3],
                        aB + mt * (16 * LDS_H * 2) + k16 * 32);
#pragma unroll
            for (int p = 0; p < 4; p++)
                ldsm_x4(b[2 * p][0], b[2 * p][1], b[2 * p + 1][0], b[2 * p + 1][1],
                        bB + p * (16 * LDS_H * 2) + k16 * 32);
#pragma unroll
            for (int nt = 0; nt < 8; nt++)
#pragma unroll
                for (int mt = 0; mt < 2; mt++) mma16816(acc[mt][nt], a[mt], b[nt]);
        }
    };

    // 3-stage circular pipeline, one __syncthreads per chunk
    constexpr int G = NPROD * 8;
    load_chunk(0, 0);
    CP_COMMIT();
    load_chunk(1, 1);
    CP_COMMIT();
    for (int g = 0; g < G; ++g) {
        if (g + 1 < G) { CP_WAIT1(); } else { CP_WAIT0(); }   // chunk g arrived
        __syncthreads();                        // all warps see chunk g; stage free
        if (g + 2 < G) {
            load_chunk(g + 2, (g + 2) % STAGES);
            CP_COMMIT();
        }
        compute(g % STAGES);
    }

#pragma unroll
    for (int mt = 0; mt < 2; mt++)
#pragma unroll
        for (int half = 0; half < 2; half++) {
            const int m = ybase + wr * 32 + mt * 16 + (lane >> 2) + half * 8;
            float* Crow = C + (size_t)m * kD + jbase + wc * 64;
#pragma unroll
            for (int nt = 0; nt < 8; nt++) {
                const int col = nt * 8 + (lane & 3) * 2;
                float2 v = {acc[mt][nt][half * 2], acc[mt][nt][half * 2 + 1]};
                if (BIAS) {
                    v.x += bias[jbase + wc * 64 + col];
                    v.y += bias[jbase + wc * 64 + col + 1];
                }
                *(float2*)(Crow + col) = v;
            }
        }
}

// grid 6144: blockIdx = mtile*12 + w*4 + ntile (A-split L2 reuse across w,nt)
__global__ __launch_bounds__(256, 2) void qkv_mma() {
    const int bx = blockIdx.x;
    const int mtile = bx / 12, sub = bx % 12, w = sub >> 2, nt = sub & 3;
    const __nv_bfloat16* w1 = g_ws + (size_t)(2 * w) * kWEl;
    const __nv_bfloat16* w2 = w1 + kWEl;
    // products: x1*w1 + x1*w2 + x2*w1
    const __nv_bfloat16* Ap[3] = {g_as, g_as, g_as + kTMD};
    const __nv_bfloat16* Wb[3] = {w1, w2, w1};
    gemm_hmma<3, false>(Ap, Wb, g_pre + (size_t)w * kTMD, nullptr, mtile * BM, nt * BN);
}

// grid 2048
__global__ __launch_bounds__(256, 2) void proj_mma(const float* __restrict__ bp,
                                                   float* __restrict__ out) {
    const int mtile = blockIdx.x >> 2, nt = blockIdx.x & 3;
    const __nv_bfloat16* wp1 = g_ws + (size_t)6 * kWEl;    // Wp splits
    const __nv_bfloat16* Ap[2] = {g_o, g_o};
    const __nv_bfloat16* Wb[2] = {wp1, wp1 + kWEl};
    gemm_hmma<2, true>(Ap, Wb, out, bp, mtile * BM, nt * BN);
}

// ------------------------------ prep kernels -------------------------------
__device__ __forceinline__ void split2(float a, __nv_bfloat16& s1, __nv_bfloat16& s2) {
    s1 = __float2bfloat16(a);
    s2 = __float2bfloat16(a - __bfloat162float(s1));
}

__global__ void reset_cnt() { if (threadIdx.x == 0) g_cnt = 0; }

__global__ void split_x(const float* __restrict__ x) {
    const size_t i4 = ((size_t)blockIdx.x * 256 + threadIdx.x) * 4;
    float4 v = *(const float4*)(x + i4);
    __nv_bfloat16 a[4], b[4];
    split2(v.x, a[0], b[0]); split2(v.y, a[1], b[1]);
    split2(v.z, a[2], b[2]); split2(v.w, a[3], b[3]);
    *(uint2*)(g_as + i4)        = *(uint2*)a;
    *(uint2*)(g_as + kTMD + i4) = *(uint2*)b;
}

__global__ void split_w(const float* __restrict__ Wq, const float* __restrict__ Wk,
                        const float* __restrict__ Wv, const float* __restrict__ Wpj) {
    const int i4 = (blockIdx.x * 256 + threadIdx.x) * 4;
    const int w = i4 >> 18, off = i4 & (kWEl - 1);
    const float* src = (w == 0) ? Wq : (w == 1) ? Wk : (w == 2) ? Wv : Wpj;
    float4 v = *(const float4*)(src + off);
    __nv_bfloat16 a[4], b[4];
    split2(v.x, a[0], b[0]); split2(v.y, a[1], b[1]);
    split2(v.z, a[2], b[2]); split2(v.w, a[3], b[3]);
    __nv_bfloat16* base = g_ws + (size_t)(2 * w) * kWEl + off;
    *(uint2*)(base)        = *(uint2*)a;
    *(uint2*)(base + kWEl) = *(uint2*)b;
}

// LIF + cumsum + q*context on approx pre-acts; flags borderline elements.
__global__ void lif_fuse() {
    const size_t i4 = ((size_t)blockIdx.x * 256 + threadIdx.x) * 4;
    float mq[4] = {0, 0, 0, 0}, mk[4] = {0, 0, 0, 0};
    float mv[4] = {0, 0, 0, 0}, cx[4] = {0, 0, 0, 0};
    bool bad[4] = {false, false, false, false};
#pragma unroll
    for (int t = 0; t < kT; t++) {
        const size_t o = (size_t)t * kMD + i4;
        float4 xq = *(const float4*)(g_pre + o);
        float4 xk = *(const float4*)(g_pre + kTMD + o);
        float4 xv = *(const float4*)(g_pre + 2 * kTMD + o);
        __nv_bfloat16 ob[4];
#pragma unroll
        for (int e = 0; e < 4; e++) {
            mq[e] = mq[e] * 0.9f + (&xq.x)[e];
            mk[e] = mk[e] * 0.9f + (&xk.x)[e];
            mv[e] = mv[e] * 0.9f + (&xv.x)[e];
            bad[e] = bad[e] | (fabsf(mq[e] - 1.0f) < kDelta)
                            | (fabsf(mk[e] - 1.0f) < kDelta)
                            | (fabsf(mv[e] - 1.0f) < kDelta);
            const float sq = (mq[e] >= 1.0f) ? 1.f : 0.f;
            const float sk = (mk[e] >= 1.0f) ? 1.f : 0.f;
            const float sv = (mv[e] >= 1.0f) ? 1.f : 0.f;
            mq[e] -= sq; mk[e] -= sk; mv[e] -= sv;
            cx[e] += sk * sv;
            ob[e] = __float2bfloat16(sq * cx[e]);   // exact (0..4)
        }
        *(uint2*)(g_o + o) = *(uint2*)ob;
    }
#pragma unroll
    for (int e = 0; e < 4; e++)
        if (bad[e]) {
            int p = atomicAdd(&g_cnt, 1);
            if (p < kFlagCap) g_flags[p] = (int)(i4 + e);
        }
}

// Exact recompute of flagged elements: serial k-ascending fp32 fmaf chains
// (bit-identical to reference GEMM), exact LIF redo overwriting g_o.
__global__ void fix_flagged(const float* __restrict__ x, const float* __restrict__ Wq,
                            const float* __restrict__ Wk, const float* __restrict__ Wv) {
    const int n = g_cnt < kFlagCap ? g_cnt : kFlagCap;
    for (int j = blockIdx.x * blockDim.x + threadIdx.x; j < n;
         j += gridDim.x * blockDim.x) {
        const int e = g_flags[j];
        const int row = e >> 9, d = e & (kD - 1);
        const float* wq = Wq + (size_t)d * kD;
        const float* wk = Wk + (size_t)d * kD;
        const float* wv = Wv + (size_t)d * kD;
        float mq = 0.f, mk = 0.f, mv = 0.f, cx = 0.f;
#pragma unroll 1
        for (int t = 0; t < kT; t++) {
            const float* xr = x + ((size_t)t * kM + row) * kD;
            float aq = 0.f, ak = 0.f, av = 0.f;
            for (int k = 0; k < kD; k++) {        // strict ascending-k chains
                const float xv_ = xr[k];
                aq = fmaf(xv_, wq[k], aq);
                ak = fmaf(xv_, wk[k], ak);
                av = fmaf(xv_, wv[k], av);
            }
            mq = mq * 0.9f + aq;
            mk = mk * 0.9f + ak;
            mv = mv * 0.9f + av;
            const float sq = (mq >= 1.0f) ? 1.f : 0.f;
            const float sk = (mk >= 1.0f) ? 1.f : 0.f;
            const float sv = (mv >= 1.0f) ? 1.f : 0.f;
            mq -= sq; mk -= sk; mv -= sv;
            cx += sk * sv;
            g_o[(size_t)t * kMD + e] = __float2bfloat16(sq * cx);
        }
    }
}

// ------------------------------ launcher -----------------------------------
extern "C" void kernel_launch(void* const* d_in, const int* in_sizes, int n_in,
                              void* d_out, int out_size) {
    const float* x   = (const float*)d_in[0];
    const float* Wq  = (const float*)d_in[1];
    const float* Wk  = (const float*)d_in[2];
    const float* Wv  = (const float*)d_in[3];
    const float* Wpj = (const float*)d_in[4];
    const float* bp  = (const float*)d_in[5];
    float* out = (float*)d_out;

    cudaFuncSetAttribute(qkv_mma, cudaFuncAttributeMaxDynamicSharedMemorySize, (int)SMEM_BYTES);
    cudaFuncSetAttribute(proj_mma, cudaFuncAttributeMaxDynamicSharedMemorySize, (int)SMEM_BYTES);

    reset_cnt<<<1, 32>>>();
    split_w<<<kWEl / 256, 256>>>(Wq, Wk, Wv, Wpj);
    split_x<<<(int)(kTMD / 1024), 256>>>(x);
    qkv_mma<<<6144, 256, SMEM_BYTES>>>();
    lif_fuse<<<(int)(kMD / 1024), 256>>>();
    fix_flagged<<<1024, 128>>>(x, Wq, Wk, Wv);
    proj_mma<<<2048, 256, SMEM_BYTES>>>(bp, out);
}

// round 13
// speedup vs baseline: 1.1837x; 1.1169x over previous
#include <cuda_runtime.h>
#include <cuda_bf16.h>
#include <cstdint>

// ---------------------------------------------------------------------------
// SpikingSelfAttention, compute_100-safe (HMMA mma.sync, no tcgen05).
//   QKV:  merged 3-product 2-way bf16-split HMMA (x1w1 + x1w2 + x2w1),
//         tiles {x1,x2,w1,w2} loaded ONCE per k-chunk (products ai+bi<=1)
//   LIF:  flags elements with any |mem-1| < 2e-4
//   FIX:  flagged elements recomputed bit-exactly (serial fp32 fmaf chains)
//   proj: o = q_spike*ctx exact integer -> merged 2-product HMMA (Wp split)
// Round 13: merged products, KC=32, SW64 swizzle (no pad), 16 syncs/CTA
// ---------------------------------------------------------------------------

namespace {
constexpr int    kT    = 4;
constexpr int    kM    = 16384;               // B*N
constexpr int    kD    = 512;
constexpr int    kRows = kT * kM;             // 65536
constexpr size_t kMD   = (size_t)kM * kD;     // 8388608
constexpr size_t kTMD  = (size_t)kRows * kD;  // 33554432
constexpr int    kWEl  = kD * kD;             // 262144

constexpr int BM = 128, BN = 128, KC = 32;
constexpr int G_CHUNKS = kD / KC;             // 16
constexpr int TILE_B = BM * KC * 2;           // 8192 bytes per tile
constexpr int STAGES = 3;

constexpr float  kDelta = 2e-4f;              // borderline flag margin
constexpr int    kFlagCap = 1 << 21;
}

// Scratch (__device__ globals; allocation-free rule)
__device__ float         g_pre[3 * kTMD];     // q,k,v pre-activations (fp32)
__device__ __nv_bfloat16 g_as[2 * kTMD];      // x splits x1,x2
__device__ __nv_bfloat16 g_o[kTMD];           // q_spike*context (exact bf16)
__device__ __nv_bfloat16 g_ws[8 * kWEl];      // [w 0..3][split 0..1] weights
__device__ int           g_cnt;
__device__ int           g_flags[kFlagCap];

// ------------------------------- helpers -----------------------------------
__device__ __forceinline__ uint32_t smem_u32(const void* p) {
    uint32_t a;
    asm("{ .reg .u64 t; cvta.to.shared.u64 t, %1; cvt.u32.u64 %0, t; }" : "=r"(a) : "l"(p));
    return a;
}
#define CP16(dst, src) \
    asm volatile("cp.async.cg.shared.global [%0], [%1], 16;" :: "r"(dst), "l"(src) : "memory")
#define CP_COMMIT() asm volatile("cp.async.commit_group;" ::: "memory")
#define CP_WAIT1()  asm volatile("cp.async.wait_group 1;" ::: "memory")
#define CP_WAIT0()  asm volatile("cp.async.wait_group 0;" ::: "memory")

__device__ __forceinline__ void ldsm_x4(uint32_t& r0, uint32_t& r1,
                                        uint32_t& r2, uint32_t& r3, uint32_t addr) {
    asm volatile("ldmatrix.sync.aligned.m8n8.x4.shared.b16 {%0,%1,%2,%3}, [%4];"
                 : "=r"(r0), "=r"(r1), "=r"(r2), "=r"(r3) : "r"(addr));
}
__device__ __forceinline__ void mma16816(float* c, const uint32_t* a, const uint32_t* b) {
    asm volatile(
        "mma.sync.aligned.m16n8k16.row.col.f32.bf16.bf16.f32 "
        "{%0,%1,%2,%3}, {%4,%5,%6,%7}, {%8,%9}, {%0,%1,%2,%3};"
        : "+f"(c[0]), "+f"(c[1]), "+f"(c[2]), "+f"(c[3])
        : "r"(a[0]), "r"(a[1]), "r"(a[2]), "r"(a[3]), "r"(b[0]), "r"(b[1]));
}

// --------------------- merged-product HMMA GEMM core -----------------------
// acc = sum over products (ai,bi) with ai+bi<=1 of A[ai] * B[bi]^T  (+ bias)
// Tiles per k-chunk (KC=32): NA A-tiles + NB B-tiles, each 128x32, SW64 swizzle.
template <int NA, int NB, bool BIAS>
__device__ __forceinline__ void gemm_merged(const __nv_bfloat16* const (&Ap)[NA],
                                            const __nv_bfloat16* const (&Bp)[NB],
                                            float* __restrict__ C,
                                            const float* __restrict__ bias,
                                            int ybase, int jbase) {
    constexpr int NT = NA + NB;
    constexpr int STAGE_B = NT * TILE_B;
    extern __shared__ __nv_bfloat16 sm[];
    const uint32_t smb = smem_u32(sm);
    const int tid = threadIdx.x, lane = tid & 31, wid = tid >> 5;
    const int wr = wid & 3, wc = wid >> 2;     // warp grid 4(m) x 2(n)

    float acc[2][8][4];
#pragma unroll
    for (int mt = 0; mt < 2; mt++)
#pragma unroll
        for (int nt = 0; nt < 8; nt++)
#pragma unroll
            for (int e = 0; e < 4; e++) acc[mt][nt][e] = 0.f;

    // ---- cp.async staging: per tile 128 rows x 2 passes, 16B units ----
    const int srow = tid >> 2;                 // 0..63 (+64 second pass)
    const int sunit = tid & 3;                 // 16B unit within 64B row
    // SW64 swizzle of (row*64 + unit*16): xor unit index by (row>>1)&3
    auto load_chunk = [&](int g, int buf) {
        const uint32_t dst0 = smb + buf * STAGE_B;
#pragma unroll
        for (int t = 0; t < NT; t++) {
            const __nv_bfloat16* src =
                (t < NA ? Ap[t] + (size_t)ybase * kD : Bp[t - NA] + (size_t)jbase * kD)
                + g * KC;
#pragma unroll
            for (int i = 0; i < 2; i++) {
                const int row = srow + 64 * i;
                const int swu = sunit ^ ((row >> 1) & 3);
                CP16(dst0 + t * TILE_B + row * 64 + swu * 16,
                     src + (size_t)row * kD + sunit * 8);
            }
        }
    };

    // ---- ldmatrix per-lane constants ----
    const int l7 = lane & 7, sel = lane >> 3;
    uint32_t aRow[2], aXr[2];
#pragma unroll
    for (int mt = 0; mt < 2; mt++) {
        const int r = wr * 32 + mt * 16 + l7 + (sel & 1) * 8;
        aRow[mt] = (uint32_t)(r * 64);
        aXr[mt]  = (uint32_t)((r >> 1) & 3);
    }
    const uint32_t aU = (uint32_t)(sel >> 1);    // + 2*h
    uint32_t bRow[4], bXr[4];
#pragma unroll
    for (int p = 0; p < 4; p++) {
        const int r = wc * 64 + p * 16 + l7 + (sel >> 1) * 8;
        bRow[p] = (uint32_t)(r * 64);
        bXr[p]  = (uint32_t)((r >> 1) & 3);
    }
    const uint32_t bU = (uint32_t)(sel & 1);     // + 2*h

    auto compute = [&](int buf) {
        const uint32_t base = smb + (uint32_t)(buf * STAGE_B);
#pragma unroll
        for (int h = 0; h < 2; h++) {            // two k16 steps in KC=32
            uint32_t a[NA][2][4];
#pragma unroll
            for (int ai = 0; ai < NA; ai++)
#pragma unroll
                for (int mt = 0; mt < 2; mt++)
                    ldsm_x4(a[ai][mt][0], a[ai][mt][1], a[ai][mt][2], a[ai][mt][3],
                            base + ai * TILE_B + aRow[mt]
                                 + (((aU + 2 * h) ^ aXr[mt]) << 4));
#pragma unroll
            for (int p = 0; p < 4; p++) {
                uint32_t bt[NB][2][2];
#pragma unroll
                for (int bi = 0; bi < NB; bi++)
                    ldsm_x4(bt[bi][0][0], bt[bi][0][1], bt[bi][1][0], bt[bi][1][1],
                            base + (NA + bi) * TILE_B + bRow[p]
                                 + (((bU + 2 * h) ^ bXr[p]) << 4));
#pragma unroll
                for (int ai = 0; ai < NA; ai++)
#pragma unroll
                    for (int bi = 0; bi < NB; bi++)
                        if (ai + bi <= 1)
#pragma unroll
                            for (int j = 0; j < 2; j++)
#pragma unroll
                                for (int mt = 0; mt < 2; mt++)
                                    mma16816(acc[mt][2 * p + j], a[ai][mt], bt[bi][j]);
            }
        }
    };

    // 3-stage circular pipeline, one __syncthreads per chunk
    load_chunk(0, 0);
    CP_COMMIT();
    load_chunk(1, 1);
    CP_COMMIT();
    for (int g = 0; g < G_CHUNKS; ++g) {
        if (g + 1 < G_CHUNKS) { CP_WAIT1(); } else { CP_WAIT0(); }
        __syncthreads();
        if (g + 2 < G_CHUNKS) {
            load_chunk(g + 2, (g + 2) % STAGES);
            CP_COMMIT();
        }
        compute(g % STAGES);
    }

#pragma unroll
    for (int mt = 0; mt < 2; mt++)
#pragma unroll
        for (int half = 0; half < 2; half++) {
            const int m = ybase + wr * 32 + mt * 16 + (lane >> 2) + half * 8;
            float* Crow = C + (size_t)m * kD + jbase + wc * 64;
#pragma unroll
            for (int nt = 0; nt < 8; nt++) {
                const int col = nt * 8 + (lane & 3) * 2;
                float2 v = {acc[mt][nt][half * 2], acc[mt][nt][half * 2 + 1]};
                if (BIAS) {
                    v.x += bias[jbase + wc * 64 + col];
                    v.y += bias[jbase + wc * 64 + col + 1];
                }
                *(float2*)(Crow + col) = v;
            }
        }
}

// grid 6144: blockIdx = mtile*12 + w*4 + ntile (A-split L2 reuse across w,nt)
__global__ __launch_bounds__(256, 2) void qkv_mma() {
    const int bx = blockIdx.x;
    const int mtile = bx / 12, sub = bx % 12, w = sub >> 2, nt = sub & 3;
    const __nv_bfloat16* w1 = g_ws + (size_t)(2 * w) * kWEl;
    const __nv_bfloat16* Ap[2] = {g_as, g_as + kTMD};
    const __nv_bfloat16* Bp[2] = {w1, w1 + kWEl};
    gemm_merged<2, 2, false>(Ap, Bp, g_pre + (size_t)w * kTMD, nullptr,
                             mtile * BM, nt * BN);
}

// grid 2048
__global__ __launch_bounds__(256, 2) void proj_mma(const float* __restrict__ bp,
                                                   float* __restrict__ out) {
    const int mtile = blockIdx.x >> 2, nt = blockIdx.x & 3;
    const __nv_bfloat16* wp1 = g_ws + (size_t)6 * kWEl;
    const __nv_bfloat16* Ap[1] = {g_o};
    const __nv_bfloat16* Bp[2] = {wp1, wp1 + kWEl};
    gemm_merged<1, 2, true>(Ap, Bp, out, bp, mtile * BM, nt * BN);
}

// ------------------------------ prep kernels -------------------------------
__device__ __forceinline__ void split2(float a, __nv_bfloat16& s1, __nv_bfloat16& s2) {
    s1 = __float2bfloat16(a);
    s2 = __float2bfloat16(a - __bfloat162float(s1));
}

__global__ void split_x(const float* __restrict__ x) {
    const size_t i4 = ((size_t)blockIdx.x * 256 + threadIdx.x) * 4;
    float4 v = *(const float4*)(x + i4);
    __nv_bfloat16 a[4], b[4];
    split2(v.x, a[0], b[0]); split2(v.y, a[1], b[1]);
    split2(v.z, a[2], b[2]); split2(v.w, a[3], b[3]);
    *(uint2*)(g_as + i4)        = *(uint2*)a;
    *(uint2*)(g_as + kTMD + i4) = *(uint2*)b;
}

__global__ void split_w(const float* __restrict__ Wq, const float* __restrict__ Wk,
                        const float* __restrict__ Wv, const float* __restrict__ Wpj) {
    if (blockIdx.x == 0 && threadIdx.x == 0) g_cnt = 0;
    const int i4 = (blockIdx.x * 256 + threadIdx.x) * 4;
    const int w = i4 >> 18, off = i4 & (kWEl - 1);
    const float* src = (w == 0) ? Wq : (w == 1) ? Wk : (w == 2) ? Wv : Wpj;
    float4 v = *(const float4*)(src + off);
    __nv_bfloat16 a[4], b[4];
    split2(v.x, a[0], b[0]); split2(v.y, a[1], b[1]);
    split2(v.z, a[2], b[2]); split2(v.w, a[3], b[3]);
    __nv_bfloat16* base = g_ws + (size_t)(2 * w) * kWEl + off;
    *(uint2*)(base)        = *(uint2*)a;
    *(uint2*)(base + kWEl) = *(uint2*)b;
}

// LIF + cumsum + q*context on approx pre-acts; flags borderline elements.
__global__ void lif_fuse() {
    const size_t i4 = ((size_t)blockIdx.x * 256 + threadIdx.x) * 4;
    float mq[4] = {0, 0, 0, 0}, mk[4] = {0, 0, 0, 0};
    float mv[4] = {0, 0, 0, 0}, cx[4] = {0, 0, 0, 0};
    bool bad[4] = {false, false, false, false};
#pragma unroll
    for (int t = 0; t < kT; t++) {
        const size_t o = (size_t)t * kMD + i4;
        float4 xq = *(const float4*)(g_pre + o);
        float4 xk = *(const float4*)(g_pre + kTMD + o);
        float4 xv = *(const float4*)(g_pre + 2 * kTMD + o);
        __nv_bfloat16 ob[4];
#pragma unroll
        for (int e = 0; e < 4; e++) {
            mq[e] = mq[e] * 0.9f + (&xq.x)[e];
            mk[e] = mk[e] * 0.9f + (&xk.x)[e];
            mv[e] = mv[e] * 0.9f + (&xv.x)[e];
            bad[e] = bad[e] | (fabsf(mq[e] - 1.0f) < kDelta)
                            | (fabsf(mk[e] - 1.0f) < kDelta)
                            | (fabsf(mv[e] - 1.0f) < kDelta);
            const float sq = (mq[e] >= 1.0f) ? 1.f : 0.f;
            const float sk = (mk[e] >= 1.0f) ? 1.f : 0.f;
            const float sv = (mv[e] >= 1.0f) ? 1.f : 0.f;
            mq[e] -= sq; mk[e] -= sk; mv[e] -= sv;
            cx[e] += sk * sv;
            ob[e] = __float2bfloat16(sq * cx[e]);   // exact (0..4)
        }
        *(uint2*)(g_o + o) = *(uint2*)ob;
    }
#pragma unroll
    for (int e = 0; e < 4; e++)
        if (bad[e]) {
            int p = atomicAdd(&g_cnt, 1);
            if (p < kFlagCap) g_flags[p] = (int)(i4 + e);
        }
}

// Exact recompute of flagged elements: serial k-ascending fp32 fmaf chains
// (bit-identical to reference GEMM), exact LIF redo overwriting g_o.
__global__ void fix_flagged(const float* __restrict__ x, const float* __restrict__ Wq,
                            const float* __restrict__ Wk, const float* __restrict__ Wv) {
    const int n = g_cnt < kFlagCap ? g_cnt : kFlagCap;
    for (int j = blockIdx.x * blockDim.x + threadIdx.x; j < n;
         j += gridDim.x * blockDim.x) {
        const int e = g_flags[j];
        const int row = e >> 9, d = e & (kD - 1);
        const float* wq = Wq + (size_t)d * kD;
        const float* wk = Wk + (size_t)d * kD;
        const float* wv = Wv + (size_t)d * kD;
        float mq = 0.f, mk = 0.f, mv = 0.f, cx = 0.f;
#pragma unroll 1
        for (int t = 0; t < kT; t++) {
            const float* xr = x + ((size_t)t * kM + row) * kD;
            float aq = 0.f, ak = 0.f, av = 0.f;
            for (int k = 0; k < kD; k++) {        // strict ascending-k chains
                const float xv_ = xr[k];
                aq = fmaf(xv_, wq[k], aq);
                ak = fmaf(xv_, wk[k], ak);
                av = fmaf(xv_, wv[k], av);
            }
            mq = mq * 0.9f + aq;
            mk = mk * 0.9f + ak;
            mv = mv * 0.9f + av;
            const float sq = (mq >= 1.0f) ? 1.f : 0.f;
            const float sk = (mk >= 1.0f) ? 1.f : 0.f;
            const float sv = (mv >= 1.0f) ? 1.f : 0.f;
            mq -= sq; mk -= sk; mv -= sv;
            cx += sk * sv;
            g_o[(size_t)t * kMD + e] = __float2bfloat16(sq * cx);
        }
    }
}

// ------------------------------ launcher -----------------------------------
extern "C" void kernel_launch(void* const* d_in, const int* in_sizes, int n_in,
                              void* d_out, int out_size) {
    const float* x   = (const float*)d_in[0];
    const float* Wq  = (const float*)d_in[1];
    const float* Wk  = (const float*)d_in[2];
    const float* Wv  = (const float*)d_in[3];
    const float* Wpj = (const float*)d_in[4];
    const float* bp  = (const float*)d_in[5];
    float* out = (float*)d_out;

    constexpr size_t QKV_SMEM  = (size_t)STAGES * 4 * TILE_B;   // 98304
    constexpr size_t PROJ_SMEM = (size_t)STAGES * 3 * TILE_B;   // 73728
    cudaFuncSetAttribute(qkv_mma, cudaFuncAttributeMaxDynamicSharedMemorySize, (int)QKV_SMEM);
    cudaFuncSetAttribute(proj_mma, cudaFuncAttributeMaxDynamicSharedMemorySize, (int)PROJ_SMEM);

    split_w<<<kWEl / 256, 256>>>(Wq, Wk, Wv, Wpj);
    split_x<<<(int)(kTMD / 1024), 256>>>(x);
    qkv_mma<<<6144, 256, QKV_SMEM>>>();
    lif_fuse<<<(int)(kMD / 1024), 256>>>();
    fix_flagged<<<1024, 128>>>(x, Wq, Wk, Wv);
    proj_mma<<<2048, 256, PROJ_SMEM>>>(bp, out);
}

// round 14
// speedup vs baseline: 1.7086x; 1.4435x over previous
#include <cuda_runtime.h>
#include <cuda_bf16.h>
#include <cstdint>

// ---------------------------------------------------------------------------
// SpikingSelfAttention, compute_100-safe (HMMA mma.sync, no tcgen05).
//   QKV:  merged 3-product 2-way bf16-split HMMA (x1w1 + x1w2 + x2w1),
//         tiles {x1,x2,w1,w2} loaded ONCE per k-chunk (products ai+bi<=1)
//   LIF:  flags elements with any |mem-1| < 1.5e-4
//   FIX:  flagged elements recomputed bit-exactly: 12 parallel strict-order
//         fp32 fmaf chains with float4 feeds (round-2-proven bit-identical)
//   proj: o = q_spike*ctx exact integer -> merged 2-product HMMA (Wp split)
// ---------------------------------------------------------------------------

namespace {
constexpr int    kT    = 4;
constexpr int    kM    = 16384;               // B*N
constexpr int    kD    = 512;
constexpr int    kRows = kT * kM;             // 65536
constexpr size_t kMD   = (size_t)kM * kD;     // 8388608
constexpr size_t kTMD  = (size_t)kRows * kD;  // 33554432
constexpr int    kWEl  = kD * kD;             // 262144

constexpr int BM = 128, BN = 128, KC = 32;
constexpr int G_CHUNKS = kD / KC;             // 16
constexpr int TILE_B = BM * KC * 2;           // 8192 bytes per tile
constexpr int STAGES = 3;

constexpr float  kDelta = 1.5e-4f;            // borderline flag margin (10 sigma)
constexpr int    kFlagCap = 1 << 21;
}

// Scratch (__device__ globals; allocation-free rule)
__device__ float         g_pre[3 * kTMD];     // q,k,v pre-activations (fp32)
__device__ __nv_bfloat16 g_as[2 * kTMD];      // x splits x1,x2
__device__ __nv_bfloat16 g_o[kTMD];           // q_spike*context (exact bf16)
__device__ __nv_bfloat16 g_ws[8 * kWEl];      // [w 0..3][split 0..1] weights
__device__ int           g_cnt;
__device__ int           g_flags[kFlagCap];

// ------------------------------- helpers -----------------------------------
__device__ __forceinline__ uint32_t smem_u32(const void* p) {
    uint32_t a;
    asm("{ .reg .u64 t; cvta.to.shared.u64 t, %1; cvt.u32.u64 %0, t; }" : "=r"(a) : "l"(p));
    return a;
}
#define CP16(dst, src) \
    asm volatile("cp.async.cg.shared.global [%0], [%1], 16;" :: "r"(dst), "l"(src) : "memory")
#define CP_COMMIT() asm volatile("cp.async.commit_group;" ::: "memory")
#define CP_WAIT1()  asm volatile("cp.async.wait_group 1;" ::: "memory")
#define CP_WAIT0()  asm volatile("cp.async.wait_group 0;" ::: "memory")

__device__ __forceinline__ void ldsm_x4(uint32_t& r0, uint32_t& r1,
                                        uint32_t& r2, uint32_t& r3, uint32_t addr) {
    asm volatile("ldmatrix.sync.aligned.m8n8.x4.shared.b16 {%0,%1,%2,%3}, [%4];"
                 : "=r"(r0), "=r"(r1), "=r"(r2), "=r"(r3) : "r"(addr));
}
__device__ __forceinline__ void mma16816(float* c, const uint32_t* a, const uint32_t* b) {
    asm volatile(
        "mma.sync.aligned.m16n8k16.row.col.f32.bf16.bf16.f32 "
        "{%0,%1,%2,%3}, {%4,%5,%6,%7}, {%8,%9}, {%0,%1,%2,%3};"
        : "+f"(c[0]), "+f"(c[1]), "+f"(c[2]), "+f"(c[3])
        : "r"(a[0]), "r"(a[1]), "r"(a[2]), "r"(a[3]), "r"(b[0]), "r"(b[1]));
}

// --------------------- merged-product HMMA GEMM core -----------------------
// acc = sum over products (ai,bi) with ai+bi<=1 of A[ai] * B[bi]^T  (+ bias)
template <int NA, int NB, bool BIAS>
__device__ __forceinline__ void gemm_merged(const __nv_bfloat16* const (&Ap)[NA],
                                            const __nv_bfloat16* const (&Bp)[NB],
                                            float* __restrict__ C,
                                            const float* __restrict__ bias,
                                            int ybase, int jbase) {
    constexpr int NT = NA + NB;
    constexpr int STAGE_B = NT * TILE_B;
    extern __shared__ __nv_bfloat16 sm[];
    const uint32_t smb = smem_u32(sm);
    const int tid = threadIdx.x, lane = tid & 31, wid = tid >> 5;
    const int wr = wid & 3, wc = wid >> 2;     // warp grid 4(m) x 2(n)

    float acc[2][8][4];
#pragma unroll
    for (int mt = 0; mt < 2; mt++)
#pragma unroll
        for (int nt = 0; nt < 8; nt++)
#pragma unroll
            for (int e = 0; e < 4; e++) acc[mt][nt][e] = 0.f;

    const int srow = tid >> 2;                 // 0..63 (+64 second pass)
    const int sunit = tid & 3;                 // 16B unit within 64B row
    auto load_chunk = [&](int g, int buf) {
        const uint32_t dst0 = smb + buf * STAGE_B;
#pragma unroll
        for (int t = 0; t < NT; t++) {
            const __nv_bfloat16* src =
                (t < NA ? Ap[t] + (size_t)ybase * kD : Bp[t - NA] + (size_t)jbase * kD)
                + g * KC;
#pragma unroll
            for (int i = 0; i < 2; i++) {
                const int row = srow + 64 * i;
                const int swu = sunit ^ ((row >> 1) & 3);
                CP16(dst0 + t * TILE_B + row * 64 + swu * 16,
                     src + (size_t)row * kD + sunit * 8);
            }
        }
    };

    const int l7 = lane & 7, sel = lane >> 3;
    uint32_t aRow[2], aXr[2];
#pragma unroll
    for (int mt = 0; mt < 2; mt++) {
        const int r = wr * 32 + mt * 16 + l7 + (sel & 1) * 8;
        aRow[mt] = (uint32_t)(r * 64);
        aXr[mt]  = (uint32_t)((r >> 1) & 3);
    }
    const uint32_t aU = (uint32_t)(sel >> 1);
    uint32_t bRow[4], bXr[4];
#pragma unroll
    for (int p = 0; p < 4; p++) {
        const int r = wc * 64 + p * 16 + l7 + (sel >> 1) * 8;
        bRow[p] = (uint32_t)(r * 64);
        bXr[p]  = (uint32_t)((r >> 1) & 3);
    }
    const uint32_t bU = (uint32_t)(sel & 1);

    auto compute = [&](int buf) {
        const uint32_t base = smb + (uint32_t)(buf * STAGE_B);
#pragma unroll
        for (int h = 0; h < 2; h++) {
            uint32_t a[NA][2][4];
#pragma unroll
            for (int ai = 0; ai < NA; ai++)
#pragma unroll
                for (int mt = 0; mt < 2; mt++)
                    ldsm_x4(a[ai][mt][0], a[ai][mt][1], a[ai][mt][2], a[ai][mt][3],
                            base + ai * TILE_B + aRow[mt]
                                 + (((aU + 2 * h) ^ aXr[mt]) << 4));
#pragma unroll
            for (int p = 0; p < 4; p++) {
                uint32_t bt[NB][2][2];
#pragma unroll
                for (int bi = 0; bi < NB; bi++)
                    ldsm_x4(bt[bi][0][0], bt[bi][0][1], bt[bi][1][0], bt[bi][1][1],
                            base + (NA + bi) * TILE_B + bRow[p]
                                 + (((bU + 2 * h) ^ bXr[p]) << 4));
#pragma unroll
                for (int ai = 0; ai < NA; ai++)
#pragma unroll
                    for (int bi = 0; bi < NB; bi++)
                        if (ai + bi <= 1)
#pragma unroll
                            for (int j = 0; j < 2; j++)
#pragma unroll
                                for (int mt = 0; mt < 2; mt++)
                                    mma16816(acc[mt][2 * p + j], a[ai][mt], bt[bi][j]);
            }
        }
    };

    load_chunk(0, 0);
    CP_COMMIT();
    load_chunk(1, 1);
    CP_COMMIT();
    for (int g = 0; g < G_CHUNKS; ++g) {
        if (g + 1 < G_CHUNKS) { CP_WAIT1(); } else { CP_WAIT0(); }
        __syncthreads();
        if (g + 2 < G_CHUNKS) {
            load_chunk(g + 2, (g + 2) % STAGES);
            CP_COMMIT();
        }
        compute(g % STAGES);
    }

#pragma unroll
    for (int mt = 0; mt < 2; mt++)
#pragma unroll
        for (int half = 0; half < 2; half++) {
            const int m = ybase + wr * 32 + mt * 16 + (lane >> 2) + half * 8;
            float* Crow = C + (size_t)m * kD + jbase + wc * 64;
#pragma unroll
            for (int nt = 0; nt < 8; nt++) {
                const int col = nt * 8 + (lane & 3) * 2;
                float2 v = {acc[mt][nt][half * 2], acc[mt][nt][half * 2 + 1]};
                if (BIAS) {
                    v.x += bias[jbase + wc * 64 + col];
                    v.y += bias[jbase + wc * 64 + col + 1];
                }
                *(float2*)(Crow + col) = v;
            }
        }
}

// grid 6144: blockIdx = mtile*12 + w*4 + ntile (A-split L2 reuse across w,nt)
__global__ __launch_bounds__(256, 2) void qkv_mma() {
    const int bx = blockIdx.x;
    const int mtile = bx / 12, sub = bx % 12, w = sub >> 2, nt = sub & 3;
    const __nv_bfloat16* w1 = g_ws + (size_t)(2 * w) * kWEl;
    const __nv_bfloat16* Ap[2] = {g_as, g_as + kTMD};
    const __nv_bfloat16* Bp[2] = {w1, w1 + kWEl};
    gemm_merged<2, 2, false>(Ap, Bp, g_pre + (size_t)w * kTMD, nullptr,
                             mtile * BM, nt * BN);
}

// grid 2048
__global__ __launch_bounds__(256, 2) void proj_mma(const float* __restrict__ bp,
                                                   float* __restrict__ out) {
    const int mtile = blockIdx.x >> 2, nt = blockIdx.x & 3;
    const __nv_bfloat16* wp1 = g_ws + (size_t)6 * kWEl;
    const __nv_bfloat16* Ap[1] = {g_o};
    const __nv_bfloat16* Bp[2] = {wp1, wp1 + kWEl};
    gemm_merged<1, 2, true>(Ap, Bp, out, bp, mtile * BM, nt * BN);
}

// ------------------------------ prep kernels -------------------------------
__device__ __forceinline__ void split2(float a, __nv_bfloat16& s1, __nv_bfloat16& s2) {
    s1 = __float2bfloat16(a);
    s2 = __float2bfloat16(a - __bfloat162float(s1));
}

__global__ void split_x(const float* __restrict__ x) {
    const size_t i4 = ((size_t)blockIdx.x * 256 + threadIdx.x) * 4;
    float4 v = *(const float4*)(x + i4);
    __nv_bfloat16 a[4], b[4];
    split2(v.x, a[0], b[0]); split2(v.y, a[1], b[1]);
    split2(v.z, a[2], b[2]); split2(v.w, a[3], b[3]);
    *(uint2*)(g_as + i4)        = *(uint2*)a;
    *(uint2*)(g_as + kTMD + i4) = *(uint2*)b;
}

__global__ void split_w(const float* __restrict__ Wq, const float* __restrict__ Wk,
                        const float* __restrict__ Wv, const float* __restrict__ Wpj) {
    if (blockIdx.x == 0 && threadIdx.x == 0) g_cnt = 0;
    const int i4 = (blockIdx.x * 256 + threadIdx.x) * 4;
    const int w = i4 >> 18, off = i4 & (kWEl - 1);
    const float* src = (w == 0) ? Wq : (w == 1) ? Wk : (w == 2) ? Wv : Wpj;
    float4 v = *(const float4*)(src + off);
    __nv_bfloat16 a[4], b[4];
    split2(v.x, a[0], b[0]); split2(v.y, a[1], b[1]);
    split2(v.z, a[2], b[2]); split2(v.w, a[3], b[3]);
    __nv_bfloat16* base = g_ws + (size_t)(2 * w) * kWEl + off;
    *(uint2*)(base)        = *(uint2*)a;
    *(uint2*)(base + kWEl) = *(uint2*)b;
}

// LIF + cumsum + q*context on approx pre-acts; flags borderline elements.
__global__ void lif_fuse() {
    const size_t i4 = ((size_t)blockIdx.x * 256 + threadIdx.x) * 4;
    float mq[4] = {0, 0, 0, 0}, mk[4] = {0, 0, 0, 0};
    float mv[4] = {0, 0, 0, 0}, cx[4] = {0, 0, 0, 0};
    bool bad[4] = {false, false, false, false};
#pragma unroll
    for (int t = 0; t < kT; t++) {
        const size_t o = (size_t)t * kMD + i4;
        float4 xq = *(const float4*)(g_pre + o);
        float4 xk = *(const float4*)(g_pre + kTMD + o);
        float4 xv = *(const float4*)(g_pre + 2 * kTMD + o);
        __nv_bfloat16 ob[4];
#pragma unroll
        for (int e = 0; e < 4; e++) {
            mq[e] = mq[e] * 0.9f + (&xq.x)[e];
            mk[e] = mk[e] * 0.9f + (&xk.x)[e];
            mv[e] = mv[e] * 0.9f + (&xv.x)[e];
            bad[e] = bad[e] | (fabsf(mq[e] - 1.0f) < kDelta)
                            | (fabsf(mk[e] - 1.0f) < kDelta)
                            | (fabsf(mv[e] - 1.0f) < kDelta);
            const float sq = (mq[e] >= 1.0f) ? 1.f : 0.f;
            const float sk = (mk[e] >= 1.0f) ? 1.f : 0.f;
            const float sv = (mv[e] >= 1.0f) ? 1.f : 0.f;
            mq[e] -= sq; mk[e] -= sk; mv[e] -= sv;
            cx[e] += sk * sv;
            ob[e] = __float2bfloat16(sq * cx[e]);   // exact (0..4)
        }
        *(uint2*)(g_o + o) = *(uint2*)ob;
    }
#pragma unroll
    for (int e = 0; e < 4; e++)
        if (bad[e]) {
            int p = atomicAdd(&g_cnt, 1);
            if (p < kFlagCap) g_flags[p] = (int)(i4 + e);
        }
}

// Exact recompute of flagged elements. 12 independent strict-k-ascending fp32
// fmaf chains (aq/ak/av x 4 timesteps) fed by float4 loads: identical rounding
// sequence to the reference GEMM (round-2 proven), 4x fewer LDGs, latency
// fully covered (48 FMA per 7 LDG.128). Then exact LIF redo overwriting g_o.
__global__ void fix_flagged(const float* __restrict__ x, const float* __restrict__ Wq,
                            const float* __restrict__ Wk, const float* __restrict__ Wv) {
    const int n = g_cnt < kFlagCap ? g_cnt : kFlagCap;
    for (int j = blockIdx.x * blockDim.x + threadIdx.x; j < n;
         j += gridDim.x * blockDim.x) {
        const int e = g_flags[j];
        const int row = e >> 9, d = e & (kD - 1);
        const float4* wq4 = (const float4*)(Wq + (size_t)d * kD);
        const float4* wk4 = (const float4*)(Wk + (size_t)d * kD);
        const float4* wv4 = (const float4*)(Wv + (size_t)d * kD);
        const float4* xr4[kT];
#pragma unroll
        for (int t = 0; t < kT; t++)
            xr4[t] = (const float4*)(x + ((size_t)t * kM + row) * kD);

        float aq[kT] = {0, 0, 0, 0}, ak[kT] = {0, 0, 0, 0}, av[kT] = {0, 0, 0, 0};
        for (int k4 = 0; k4 < kD / 4; k4++) {     // strict ascending k per chain
            const float4 wqv = wq4[k4], wkv = wk4[k4], wvv = wv4[k4];
#pragma unroll
            for (int t = 0; t < kT; t++) {
                const float4 xv = xr4[t][k4];
                aq[t] = fmaf(xv.x, wqv.x, aq[t]);
                aq[t] = fmaf(xv.y, wqv.y, aq[t]);
                aq[t] = fmaf(xv.z, wqv.z, aq[t]);
                aq[t] = fmaf(xv.w, wqv.w, aq[t]);
                ak[t] = fmaf(xv.x, wkv.x, ak[t]);
                ak[t] = fmaf(xv.y, wkv.y, ak[t]);
                ak[t] = fmaf(xv.z, wkv.z, ak[t]);
                ak[t] = fmaf(xv.w, wkv.w, ak[t]);
                av[t] = fmaf(xv.x, wvv.x, av[t]);
                av[t] = fmaf(xv.y, wvv.y, av[t]);
                av[t] = fmaf(xv.z, wvv.z, av[t]);
                av[t] = fmaf(xv.w, wvv.w, av[t]);
            }
        }

        float mq = 0.f, mk = 0.f, mv = 0.f, cx = 0.f;
#pragma unroll
        for (int t = 0; t < kT; t++) {
            mq = mq * 0.9f + aq[t];
            mk = mk * 0.9f + ak[t];
            mv = mv * 0.9f + av[t];
            const float sq = (mq >= 1.0f) ? 1.f : 0.f;
            const float sk = (mk >= 1.0f) ? 1.f : 0.f;
            const float sv = (mv >= 1.0f) ? 1.f : 0.f;
            mq -= sq; mk -= sk; mv -= sv;
            cx += sk * sv;
            g_o[(size_t)t * kMD + e] = __float2bfloat16(sq * cx);
        }
    }
}

// ------------------------------ launcher -----------------------------------
extern "C" void kernel_launch(void* const* d_in, const int* in_sizes, int n_in,
                              void* d_out, int out_size) {
    const float* x   = (const float*)d_in[0];
    const float* Wq  = (const float*)d_in[1];
    const float* Wk  = (const float*)d_in[2];
    const float* Wv  = (const float*)d_in[3];
    const float* Wpj = (const float*)d_in[4];
    const float* bp  = (const float*)d_in[5];
    float* out = (float*)d_out;

    constexpr size_t QKV_SMEM  = (size_t)STAGES * 4 * TILE_B;   // 98304
    constexpr size_t PROJ_SMEM = (size_t)STAGES * 3 * TILE_B;   // 73728
    cudaFuncSetAttribute(qkv_mma, cudaFuncAttributeMaxDynamicSharedMemorySize, (int)QKV_SMEM);
    cudaFuncSetAttribute(proj_mma, cudaFuncAttributeMaxDynamicSharedMemorySize, (int)PROJ_SMEM);

    split_w<<<kWEl / 256, 256>>>(Wq, Wk, Wv, Wpj);
    split_x<<<(int)(kTMD / 1024), 256>>>(x);
    qkv_mma<<<6144, 256, QKV_SMEM>>>();
    lif_fuse<<<(int)(kMD / 1024), 256>>>();
    fix_flagged<<<1024, 128>>>(x, Wq, Wk, Wv);
    proj_mma<<<2048, 256, PROJ_SMEM>>>(bp, out);
}

// round 15
// speedup vs baseline: 1.8439x; 1.0791x over previous
#include <cuda_runtime.h>
#include <cuda_fp16.h>
#include <cstdint>

// ---------------------------------------------------------------------------
// SpikingSelfAttention, compute_100-safe (HMMA mma.sync, no tcgen05).
//   QKV:  merged 3-product 2-way fp16-split HMMA (x1w1 + x1w2 + x2w1);
//         pre-act err ~1e-6 (fp32-accum-ordering floor)
//   LIF:  flags elements with any |mem-1| < 5e-5  (~40 sigma -> ~2e3 flags)
//   FIX:  flagged elements recomputed bit-exactly (12 parallel strict-order
//         fp32 fmaf chains, float4 feeds)
//   proj: o = q_spike*ctx exact integer in fp16 -> SINGLE-product HMMA
//         (Wp fp16, out rel err ~1.4e-4 << 1e-3)
// ---------------------------------------------------------------------------

namespace {
constexpr int    kT    = 4;
constexpr int    kM    = 16384;               // B*N
constexpr int    kD    = 512;
constexpr int    kRows = kT * kM;             // 65536
constexpr size_t kMD   = (size_t)kM * kD;     // 8388608
constexpr size_t kTMD  = (size_t)kRows * kD;  // 33554432
constexpr int    kWEl  = kD * kD;             // 262144

constexpr int BM = 128, BN = 128, KC = 32;
constexpr int G_CHUNKS = kD / KC;             // 16
constexpr int TILE_B = BM * KC * 2;           // 8192 bytes per tile
constexpr int STAGES = 3;

constexpr float  kDelta = 5e-5f;              // borderline flag margin
constexpr int    kFlagCap = 1 << 21;
}

// Scratch (__device__ globals; allocation-free rule)
__device__ float  g_pre[3 * kTMD];            // q,k,v pre-activations (fp32)
__device__ __half g_as[2 * kTMD];             // x splits x1,x2 (fp16)
__device__ __half g_o[kTMD];                  // q_spike*context (exact fp16)
__device__ __half g_ws[8 * kWEl];             // [0..5]=qkv w1,w2; [6]=Wp
__device__ int    g_cnt;
__device__ int    g_flags[kFlagCap];

// ------------------------------- helpers -----------------------------------
__device__ __forceinline__ uint32_t smem_u32(const void* p) {
    uint32_t a;
    asm("{ .reg .u64 t; cvta.to.shared.u64 t, %1; cvt.u32.u64 %0, t; }" : "=r"(a) : "l"(p));
    return a;
}
#define CP16(dst, src) \
    asm volatile("cp.async.cg.shared.global [%0], [%1], 16;" :: "r"(dst), "l"(src) : "memory")
#define CP_COMMIT() asm volatile("cp.async.commit_group;" ::: "memory")
#define CP_WAIT1()  asm volatile("cp.async.wait_group 1;" ::: "memory")
#define CP_WAIT0()  asm volatile("cp.async.wait_group 0;" ::: "memory")

__device__ __forceinline__ void ldsm_x4(uint32_t& r0, uint32_t& r1,
                                        uint32_t& r2, uint32_t& r3, uint32_t addr) {
    asm volatile("ldmatrix.sync.aligned.m8n8.x4.shared.b16 {%0,%1,%2,%3}, [%4];"
                 : "=r"(r0), "=r"(r1), "=r"(r2), "=r"(r3) : "r"(addr));
}
__device__ __forceinline__ void mma16816(float* c, const uint32_t* a, const uint32_t* b) {
    asm volatile(
        "mma.sync.aligned.m16n8k16.row.col.f32.f16.f16.f32 "
        "{%0,%1,%2,%3}, {%4,%5,%6,%7}, {%8,%9}, {%0,%1,%2,%3};"
        : "+f"(c[0]), "+f"(c[1]), "+f"(c[2]), "+f"(c[3])
        : "r"(a[0]), "r"(a[1]), "r"(a[2]), "r"(a[3]), "r"(b[0]), "r"(b[1]));
}

// --------------------- merged-product HMMA GEMM core -----------------------
// acc = sum over products (ai,bi) with ai+bi<=1 of A[ai] * B[bi]^T  (+ bias)
template <int NA, int NB, bool BIAS>
__device__ __forceinline__ void gemm_merged(const __half* const (&Ap)[NA],
                                            const __half* const (&Bp)[NB],
                                            float* __restrict__ C,
                                            const float* __restrict__ bias,
                                            int ybase, int jbase) {
    constexpr int NT = NA + NB;
    constexpr int STAGE_B = NT * TILE_B;
    extern __shared__ __half sm[];
    const uint32_t smb = smem_u32(sm);
    const int tid = threadIdx.x, lane = tid & 31, wid = tid >> 5;
    const int wr = wid & 3, wc = wid >> 2;     // warp grid 4(m) x 2(n)

    float acc[2][8][4];
#pragma unroll
    for (int mt = 0; mt < 2; mt++)
#pragma unroll
        for (int nt = 0; nt < 8; nt++)
#pragma unroll
            for (int e = 0; e < 4; e++) acc[mt][nt][e] = 0.f;

    const int srow = tid >> 2;                 // 0..63 (+64 second pass)
    const int sunit = tid & 3;                 // 16B unit within 64B row
    auto load_chunk = [&](int g, int buf) {
        const uint32_t dst0 = smb + buf * STAGE_B;
#pragma unroll
        for (int t = 0; t < NT; t++) {
            const __half* src =
                (t < NA ? Ap[t] + (size_t)ybase * kD : Bp[t - NA] + (size_t)jbase * kD)
                + g * KC;
#pragma unroll
            for (int i = 0; i < 2; i++) {
                const int row = srow + 64 * i;
                const int swu = sunit ^ ((row >> 1) & 3);
                CP16(dst0 + t * TILE_B + row * 64 + swu * 16,
                     src + (size_t)row * kD + sunit * 8);
            }
        }
    };

    const int l7 = lane & 7, sel = lane >> 3;
    uint32_t aRow[2], aXr[2];
#pragma unroll
    for (int mt = 0; mt < 2; mt++) {
        const int r = wr * 32 + mt * 16 + l7 + (sel & 1) * 8;
        aRow[mt] = (uint32_t)(r * 64);
        aXr[mt]  = (uint32_t)((r >> 1) & 3);
    }
    const uint32_t aU = (uint32_t)(sel >> 1);
    uint32_t bRow[4], bXr[4];
#pragma unroll
    for (int p = 0; p < 4; p++) {
        const int r = wc * 64 + p * 16 + l7 + (sel >> 1) * 8;
        bRow[p] = (uint32_t)(r * 64);
        bXr[p]  = (uint32_t)((r >> 1) & 3);
    }
    const uint32_t bU = (uint32_t)(sel & 1);

    auto compute = [&](int buf) {
        const uint32_t base = smb + (uint32_t)(buf * STAGE_B);
#pragma unroll
        for (int h = 0; h < 2; h++) {
            uint32_t a[NA][2][4];
#pragma unroll
            for (int ai = 0; ai < NA; ai++)
#pragma unroll
                for (int mt = 0; mt < 2; mt++)
                    ldsm_x4(a[ai][mt][0], a[ai][mt][1], a[ai][mt][2], a[ai][mt][3],
                            base + ai * TILE_B + aRow[mt]
                                 + (((aU + 2 * h) ^ aXr[mt]) << 4));
#pragma unroll
            for (int p = 0; p < 4; p++) {
                uint32_t bt[NB][2][2];
#pragma unroll
                for (int bi = 0; bi < NB; bi++)
                    ldsm_x4(bt[bi][0][0], bt[bi][0][1], bt[bi][1][0], bt[bi][1][1],
                            base + (NA + bi) * TILE_B + bRow[p]
                                 + (((bU + 2 * h) ^ bXr[p]) << 4));
#pragma unroll
                for (int ai = 0; ai < NA; ai++)
#pragma unroll
                    for (int bi = 0; bi < NB; bi++)
                        if (ai + bi <= 1)
#pragma unroll
                            for (int j = 0; j < 2; j++)
#pragma unroll
                                for (int mt = 0; mt < 2; mt++)
                                    mma16816(acc[mt][2 * p + j], a[ai][mt], bt[bi][j]);
            }
        }
    };

    load_chunk(0, 0);
    CP_COMMIT();
    load_chunk(1, 1);
    CP_COMMIT();
    for (int g = 0; g < G_CHUNKS; ++g) {
        if (g + 1 < G_CHUNKS) { CP_WAIT1(); } else { CP_WAIT0(); }
        __syncthreads();
        if (g + 2 < G_CHUNKS) {
            load_chunk(g + 2, (g + 2) % STAGES);
            CP_COMMIT();
        }
        compute(g % STAGES);
    }

#pragma unroll
    for (int mt = 0; mt < 2; mt++)
#pragma unroll
        for (int half = 0; half < 2; half++) {
            const int m = ybase + wr * 32 + mt * 16 + (lane >> 2) + half * 8;
            float* Crow = C + (size_t)m * kD + jbase + wc * 64;
#pragma unroll
            for (int nt = 0; nt < 8; nt++) {
                const int col = nt * 8 + (lane & 3) * 2;
                float2 v = {acc[mt][nt][half * 2], acc[mt][nt][half * 2 + 1]};
                if (BIAS) {
                    v.x += bias[jbase + wc * 64 + col];
                    v.y += bias[jbase + wc * 64 + col + 1];
                }
                *(float2*)(Crow + col) = v;
            }
        }
}

// grid 6144: blockIdx = mtile*12 + w*4 + ntile (A-split L2 reuse across w,nt)
__global__ __launch_bounds__(256, 2) void qkv_mma() {
    const int bx = blockIdx.x;
    const int mtile = bx / 12, sub = bx % 12, w = sub >> 2, nt = sub & 3;
    const __half* w1 = g_ws + (size_t)(2 * w) * kWEl;
    const __half* Ap[2] = {g_as, g_as + kTMD};
    const __half* Bp[2] = {w1, w1 + kWEl};
    gemm_merged<2, 2, false>(Ap, Bp, g_pre + (size_t)w * kTMD, nullptr,
                             mtile * BM, nt * BN);
}

// grid 2048: single product (o exact in fp16; Wp fp16)
__global__ __launch_bounds__(256, 2) void proj_mma(const float* __restrict__ bp,
                                                   float* __restrict__ out) {
    const int mtile = blockIdx.x >> 2, nt = blockIdx.x & 3;
    const __half* Ap[1] = {g_o};
    const __half* Bp[1] = {g_ws + (size_t)6 * kWEl};
    gemm_merged<1, 1, true>(Ap, Bp, out, bp, mtile * BM, nt * BN);
}

// ------------------------------ prep kernels -------------------------------
__device__ __forceinline__ void split2(float a, __half& s1, __half& s2) {
    s1 = __float2half_rn(a);
    s2 = __float2half_rn(a - __half2float(s1));
}

__global__ void split_x(const float* __restrict__ x) {
    const size_t i4 = ((size_t)blockIdx.x * 256 + threadIdx.x) * 4;
    float4 v = *(const float4*)(x + i4);
    __half a[4], b[4];
    split2(v.x, a[0], b[0]); split2(v.y, a[1], b[1]);
    split2(v.z, a[2], b[2]); split2(v.w, a[3], b[3]);
    *(uint2*)(g_as + i4)        = *(uint2*)a;
    *(uint2*)(g_as + kTMD + i4) = *(uint2*)b;
}

__global__ void split_w(const float* __restrict__ Wq, const float* __restrict__ Wk,
                        const float* __restrict__ Wv, const float* __restrict__ Wpj) {
    if (blockIdx.x == 0 && threadIdx.x == 0) g_cnt = 0;
    const int i4 = (blockIdx.x * 256 + threadIdx.x) * 4;
    const int w = i4 >> 18, off = i4 & (kWEl - 1);
    const float* src = (w == 0) ? Wq : (w == 1) ? Wk : (w == 2) ? Wv : Wpj;
    float4 v = *(const float4*)(src + off);
    __half a[4], b[4];
    split2(v.x, a[0], b[0]); split2(v.y, a[1], b[1]);
    split2(v.z, a[2], b[2]); split2(v.w, a[3], b[3]);
    __half* base = g_ws + (size_t)(2 * w) * kWEl + off;
    *(uint2*)(base)        = *(uint2*)a;
    *(uint2*)(base + kWEl) = *(uint2*)b;   // Wp residual unused (slot 7)
}

// LIF + cumsum + q*context on approx pre-acts; flags borderline elements.
__global__ void lif_fuse() {
    const size_t i4 = ((size_t)blockIdx.x * 256 + threadIdx.x) * 4;
    float mq[4] = {0, 0, 0, 0}, mk[4] = {0, 0, 0, 0};
    float mv[4] = {0, 0, 0, 0}, cx[4] = {0, 0, 0, 0};
    bool bad[4] = {false, false, false, false};
#pragma unroll
    for (int t = 0; t < kT; t++) {
        const size_t o = (size_t)t * kMD + i4;
        float4 xq = *(const float4*)(g_pre + o);
        float4 xk = *(const float4*)(g_pre + kTMD + o);
        float4 xv = *(const float4*)(g_pre + 2 * kTMD + o);
        __half ob[4];
#pragma unroll
        for (int e = 0; e < 4; e++) {
            mq[e] = mq[e] * 0.9f + (&xq.x)[e];
            mk[e] = mk[e] * 0.9f + (&xk.x)[e];
            mv[e] = mv[e] * 0.9f + (&xv.x)[e];
            bad[e] = bad[e] | (fabsf(mq[e] - 1.0f) < kDelta)
                            | (fabsf(mk[e] - 1.0f) < kDelta)
                            | (fabsf(mv[e] - 1.0f) < kDelta);
            const float sq = (mq[e] >= 1.0f) ? 1.f : 0.f;
            const float sk = (mk[e] >= 1.0f) ? 1.f : 0.f;
            const float sv = (mv[e] >= 1.0f) ? 1.f : 0.f;
            mq[e] -= sq; mk[e] -= sk; mv[e] -= sv;
            cx[e] += sk * sv;
            ob[e] = __float2half_rn(sq * cx[e]);   // exact (0..4)
        }
        *(uint2*)(g_o + o) = *(uint2*)ob;
    }
#pragma unroll
    for (int e = 0; e < 4; e++)
        if (bad[e]) {
            int p = atomicAdd(&g_cnt, 1);
            if (p < kFlagCap) g_flags[p] = (int)(i4 + e);
        }
}

// Exact recompute of flagged elements: 12 independent strict-k-ascending fp32
// fmaf chains fed by float4 loads (bit-identical to reference), LIF redo.
__global__ void fix_flagged(const float* __restrict__ x, const float* __restrict__ Wq,
                            const float* __restrict__ Wk, const float* __restrict__ Wv) {
    const int n = g_cnt < kFlagCap ? g_cnt : kFlagCap;
    for (int j = blockIdx.x * blockDim.x + threadIdx.x; j < n;
         j += gridDim.x * blockDim.x) {
        const int e = g_flags[j];
        const int row = e >> 9, d = e & (kD - 1);
        const float4* wq4 = (const float4*)(Wq + (size_t)d * kD);
        const float4* wk4 = (const float4*)(Wk + (size_t)d * kD);
        const float4* wv4 = (const float4*)(Wv + (size_t)d * kD);
        const float4* xr4[kT];
#pragma unroll
        for (int t = 0; t < kT; t++)
            xr4[t] = (const float4*)(x + ((size_t)t * kM + row) * kD);

        float aq[kT] = {0, 0, 0, 0}, ak[kT] = {0, 0, 0, 0}, av[kT] = {0, 0, 0, 0};
        for (int k4 = 0; k4 < kD / 4; k4++) {     // strict ascending k per chain
            const float4 wqv = wq4[k4], wkv = wk4[k4], wvv = wv4[k4];
#pragma unroll
            for (int t = 0; t < kT; t++) {
                const float4 xv = xr4[t][k4];
                aq[t] = fmaf(xv.x, wqv.x, aq[t]);
                aq[t] = fmaf(xv.y, wqv.y, aq[t]);
                aq[t] = fmaf(xv.z, wqv.z, aq[t]);
                aq[t] = fmaf(xv.w, wqv.w, aq[t]);
                ak[t] = fmaf(xv.x, wkv.x, ak[t]);
                ak[t] = fmaf(xv.y, wkv.y, ak[t]);
                ak[t] = fmaf(xv.z, wkv.z, ak[t]);
                ak[t] = fmaf(xv.w, wkv.w, ak[t]);
                av[t] = fmaf(xv.x, wvv.x, av[t]);
                av[t] = fmaf(xv.y, wvv.y, av[t]);
                av[t] = fmaf(xv.z, wvv.z, av[t]);
                av[t] = fmaf(xv.w, wvv.w, av[t]);
            }
        }

        float mq = 0.f, mk = 0.f, mv = 0.f, cx = 0.f;
#pragma unroll
        for (int t = 0; t < kT; t++) {
            mq = mq * 0.9f + aq[t];
            mk = mk * 0.9f + ak[t];
            mv = mv * 0.9f + av[t];
            const float sq = (mq >= 1.0f) ? 1.f : 0.f;
            const float sk = (mk >= 1.0f) ? 1.f : 0.f;
            const float sv = (mv >= 1.0f) ? 1.f : 0.f;
            mq -= sq; mk -= sk; mv -= sv;
            cx += sk * sv;
            g_o[(size_t)t * kMD + e] = __float2half_rn(sq * cx);
        }
    }
}

// ------------------------------ launcher -----------------------------------
extern "C" void kernel_launch(void* const* d_in, const int* in_sizes, int n_in,
                              void* d_out, int out_size) {
    const float* x   = (const float*)d_in[0];
    const float* Wq  = (const float*)d_in[1];
    const float* Wk  = (const float*)d_in[2];
    const float* Wv  = (const float*)d_in[3];
    const float* Wpj = (const float*)d_in[4];
    const float* bp  = (const float*)d_in[5];
    float* out = (float*)d_out;

    constexpr size_t QKV_SMEM  = (size_t)STAGES * 4 * TILE_B;   // 98304
    constexpr size_t PROJ_SMEM = (size_t)STAGES * 2 * TILE_B;   // 49152
    cudaFuncSetAttribute(qkv_mma, cudaFuncAttributeMaxDynamicSharedMemorySize, (int)QKV_SMEM);
    cudaFuncSetAttribute(proj_mma, cudaFuncAttributeMaxDynamicSharedMemorySize, (int)PROJ_SMEM);

    split_w<<<kWEl / 256, 256>>>(Wq, Wk, Wv, Wpj);
    split_x<<<(int)(kTMD / 1024), 256>>>(x);
    qkv_mma<<<6144, 256, QKV_SMEM>>>();
    lif_fuse<<<(int)(kMD / 1024), 256>>>();
    fix_flagged<<<1024, 128>>>(x, Wq, Wk, Wv);
    proj_mma<<<2048, 256, PROJ_SMEM>>>(bp, out);
}

// round 17
// speedup vs baseline: 2.3249x; 1.2609x over previous
#include <cuda_runtime.h>
#include <cuda_fp16.h>
#include <cstdint>

// ---------------------------------------------------------------------------
// SpikingSelfAttention, compute_100-safe (HMMA mma.sync, no tcgen05).
//   QKV:  SINGLE-product fp16 HMMA (x1*w1); pre-act err sigma ~2e-4
//   LIF:  flags elements with any |mem-1| < 2e-3 (10 sigma -> ~1e5 flags)
//   FIX:  flagged elements recomputed bit-exactly (12 parallel strict-order
//         fp32 fmaf chains, float4 feeds) -> spikes exact
//   proj: o = q_spike*ctx exact integer in fp16 -> single-product HMMA
// ---------------------------------------------------------------------------

namespace {
constexpr int    kT    = 4;
constexpr int    kM    = 16384;               // B*N
constexpr int    kD    = 512;
constexpr int    kRows = kT * kM;             // 65536
constexpr size_t kMD   = (size_t)kM * kD;     // 8388608
constexpr size_t kTMD  = (size_t)kRows * kD;  // 33554432
constexpr int    kWEl  = kD * kD;             // 262144

constexpr int BM = 128, BN = 128, KC = 32;
constexpr int G_CHUNKS = kD / KC;             // 16
constexpr int TILE_B = BM * KC * 2;           // 8192 bytes per tile
constexpr int STAGES = 3;

constexpr float  kDelta = 2e-3f;              // borderline flag margin (10 sigma)
constexpr int    kFlagCap = 1 << 21;
}

// Scratch (__device__ globals; allocation-free rule)
__device__ float  g_pre[3 * kTMD];            // q,k,v pre-activations (fp32)
__device__ __half g_as[kTMD];                 // x1 = fp16(x)
__device__ __half g_o[kTMD];                  // q_spike*context (exact fp16)
__device__ __half g_ws[4 * kWEl];             // w1 for q,k,v + Wp
__device__ int    g_cnt;
__device__ int    g_flags[kFlagCap];

// ------------------------------- helpers -----------------------------------
__device__ __forceinline__ uint32_t smem_u32(const void* p) {
    uint32_t a;
    asm("{ .reg .u64 t; cvta.to.shared.u64 t, %1; cvt.u32.u64 %0, t; }" : "=r"(a) : "l"(p));
    return a;
}
#define CP16(dst, src) \
    asm volatile("cp.async.cg.shared.global [%0], [%1], 16;" :: "r"(dst), "l"(src) : "memory")
#define CP_COMMIT() asm volatile("cp.async.commit_group;" ::: "memory")
#define CP_WAIT1()  asm volatile("cp.async.wait_group 1;" ::: "memory")
#define CP_WAIT0()  asm volatile("cp.async.wait_group 0;" ::: "memory")

__device__ __forceinline__ void ldsm_x4(uint32_t& r0, uint32_t& r1,
                                        uint32_t& r2, uint32_t& r3, uint32_t addr) {
    asm volatile("ldmatrix.sync.aligned.m8n8.x4.shared.b16 {%0,%1,%2,%3}, [%4];"
                 : "=r"(r0), "=r"(r1), "=r"(r2), "=r"(r3) : "r"(addr));
}
__device__ __forceinline__ void mma16816(float* c, const uint32_t* a, const uint32_t* b) {
    asm volatile(
        "mma.sync.aligned.m16n8k16.row.col.f32.f16.f16.f32 "
        "{%0,%1,%2,%3}, {%4,%5,%6,%7}, {%8,%9}, {%0,%1,%2,%3};"
        : "+f"(c[0]), "+f"(c[1]), "+f"(c[2]), "+f"(c[3])
        : "r"(a[0]), "r"(a[1]), "r"(a[2]), "r"(a[3]), "r"(b[0]), "r"(b[1]));
}

// --------------------- merged-product HMMA GEMM core -----------------------
// acc = sum over products (ai,bi) with ai+bi<=1 of A[ai] * B[bi]^T  (+ bias)
template <int NA, int NB, bool BIAS>
__device__ __forceinline__ void gemm_merged(const __half* const (&Ap)[NA],
                                            const __half* const (&Bp)[NB],
                                            float* __restrict__ C,
                                            const float* __restrict__ bias,
                                            int ybase, int jbase) {
    constexpr int NT = NA + NB;
    constexpr int STAGE_B = NT * TILE_B;
    extern __shared__ __half sm[];
    const uint32_t smb = smem_u32(sm);
    const int tid = threadIdx.x, lane = tid & 31, wid = tid >> 5;
    const int wr = wid & 3, wc = wid >> 2;     // warp grid 4(m) x 2(n)

    float acc[2][8][4];
#pragma unroll
    for (int mt = 0; mt < 2; mt++)
#pragma unroll
        for (int nt = 0; nt < 8; nt++)
#pragma unroll
            for (int e = 0; e < 4; e++) acc[mt][nt][e] = 0.f;

    const int srow = tid >> 2;                 // 0..63 (+64 second pass)
    const int sunit = tid & 3;                 // 16B unit within 64B row
    auto load_chunk = [&](int g, int buf) {
        const uint32_t dst0 = smb + buf * STAGE_B;
#pragma unroll
        for (int t = 0; t < NT; t++) {
            const __half* src =
                (t < NA ? Ap[t] + (size_t)ybase * kD : Bp[t - NA] + (size_t)jbase * kD)
                + g * KC;
#pragma unroll
            for (int i = 0; i < 2; i++) {
                const int row = srow + 64 * i;
                const int swu = sunit ^ ((row >> 1) & 3);
                CP16(dst0 + t * TILE_B + row * 64 + swu * 16,
                     src + (size_t)row * kD + sunit * 8);
            }
        }
    };

    const int l7 = lane & 7, sel = lane >> 3;
    uint32_t aRow[2], aXr[2];
#pragma unroll
    for (int mt = 0; mt < 2; mt++) {
        const int r = wr * 32 + mt * 16 + l7 + (sel & 1) * 8;
        aRow[mt] = (uint32_t)(r * 64);
        aXr[mt]  = (uint32_t)((r >> 1) & 3);
    }
    const uint32_t aU = (uint32_t)(sel >> 1);
    uint32_t bRow[4], bXr[4];
#pragma unroll
    for (int p = 0; p < 4; p++) {
        const int r = wc * 64 + p * 16 + l7 + (sel >> 1) * 8;
        bRow[p] = (uint32_t)(r * 64);
        bXr[p]  = (uint32_t)((r >> 1) & 3);
    }
    const uint32_t bU = (uint32_t)(sel & 1);

    auto compute = [&](int buf) {
        const uint32_t base = smb + (uint32_t)(buf * STAGE_B);
#pragma unroll
        for (int h = 0; h < 2; h++) {
            uint32_t a[NA][2][4];
#pragma unroll
            for (int ai = 0; ai < NA; ai++)
#pragma unroll
                for (int mt = 0; mt < 2; mt++)
                    ldsm_x4(a[ai][mt][0], a[ai][mt][1], a[ai][mt][2], a[ai][mt][3],
                            base + ai * TILE_B + aRow[mt]
                                 + (((aU + 2 * h) ^ aXr[mt]) << 4));
#pragma unroll
            for (int p = 0; p < 4; p++) {
                uint32_t bt[NB][2][2];
#pragma unroll
                for (int bi = 0; bi < NB; bi++)
                    ldsm_x4(bt[bi][0][0], bt[bi][0][1], bt[bi][1][0], bt[bi][1][1],
                            base + (NA + bi) * TILE_B + bRow[p]
                                 + (((bU + 2 * h) ^ bXr[p]) << 4));
#pragma unroll
                for (int ai = 0; ai < NA; ai++)
#pragma unroll
                    for (int bi = 0; bi < NB; bi++)
                        if (ai + bi <= 1)
#pragma unroll
                            for (int j = 0; j < 2; j++)
#pragma unroll
                                for (int mt = 0; mt < 2; mt++)
                                    mma16816(acc[mt][2 * p + j], a[ai][mt], bt[bi][j]);
            }
        }
    };

    load_chunk(0, 0);
    CP_COMMIT();
    load_chunk(1, 1);
    CP_COMMIT();
    for (int g = 0; g < G_CHUNKS; ++g) {
        if (g + 1 < G_CHUNKS) { CP_WAIT1(); } else { CP_WAIT0(); }
        __syncthreads();
        if (g + 2 < G_CHUNKS) {
            load_chunk(g + 2, (g + 2) % STAGES);
            CP_COMMIT();
        }
        compute(g % STAGES);
    }

#pragma unroll
    for (int mt = 0; mt < 2; mt++)
#pragma unroll
        for (int half = 0; half < 2; half++) {
            const int m = ybase + wr * 32 + mt * 16 + (lane >> 2) + half * 8;
            float* Crow = C + (size_t)m * kD + jbase + wc * 64;
#pragma unroll
            for (int nt = 0; nt < 8; nt++) {
                const int col = nt * 8 + (lane & 3) * 2;
                float2 v = {acc[mt][nt][half * 2], acc[mt][nt][half * 2 + 1]};
                if (BIAS) {
                    v.x += bias[jbase + wc * 64 + col];
                    v.y += bias[jbase + wc * 64 + col + 1];
                }
                *(float2*)(Crow + col) = v;
            }
        }
}

// grid 6144: blockIdx = mtile*12 + w*4 + ntile (x1-tile L2 reuse across w,nt)
__global__ __launch_bounds__(256, 2) void qkv_mma() {
    const int bx = blockIdx.x;
    const int mtile = bx / 12, sub = bx % 12, w = sub >> 2, nt = sub & 3;
    const __half* Ap[1] = {g_as};
    const __half* Bp[1] = {g_ws + (size_t)w * kWEl};
    gemm_merged<1, 1, false>(Ap, Bp, g_pre + (size_t)w * kTMD, nullptr,
                             mtile * BM, nt * BN);
}

// grid 2048: single product (o exact in fp16; Wp fp16)
__global__ __launch_bounds__(256, 2) void proj_mma(const float* __restrict__ bp,
                                                   float* __restrict__ out) {
    const int mtile = blockIdx.x >> 2, nt = blockIdx.x & 3;
    const __half* Ap[1] = {g_o};
    const __half* Bp[1] = {g_ws + (size_t)3 * kWEl};
    gemm_merged<1, 1, true>(Ap, Bp, out, bp, mtile * BM, nt * BN);
}

// ------------------------------ prep kernels -------------------------------
__global__ void split_x(const float* __restrict__ x) {
    const size_t i4 = ((size_t)blockIdx.x * 256 + threadIdx.x) * 4;
    float4 v = *(const float4*)(x + i4);
    __half a[4];
    a[0] = __float2half_rn(v.x); a[1] = __float2half_rn(v.y);
    a[2] = __float2half_rn(v.z); a[3] = __float2half_rn(v.w);
    *(uint2*)(g_as + i4) = *(uint2*)a;
}

__global__ void split_w(const float* __restrict__ Wq, const float* __restrict__ Wk,
                        const float* __restrict__ Wv, const float* __restrict__ Wpj) {
    if (blockIdx.x == 0 && threadIdx.x == 0) g_cnt = 0;
    const int i4 = (blockIdx.x * 256 + threadIdx.x) * 4;
    const int w = i4 >> 18, off = i4 & (kWEl - 1);
    const float* src = (w == 0) ? Wq : (w == 1) ? Wk : (w == 2) ? Wv : Wpj;
    float4 v = *(const float4*)(src + off);
    __half a[4];
    a[0] = __float2half_rn(v.x); a[1] = __float2half_rn(v.y);
    a[2] = __float2half_rn(v.z); a[3] = __float2half_rn(v.w);
    *(uint2*)(g_ws + (size_t)w * kWEl + off) = *(uint2*)a;
}

// LIF + cumsum + q*context on approx pre-acts; flags borderline elements.
__global__ void lif_fuse() {
    const size_t i4 = ((size_t)blockIdx.x * 256 + threadIdx.x) * 4;
    float mq[4] = {0, 0, 0, 0}, mk[4] = {0, 0, 0, 0};
    float mv[4] = {0, 0, 0, 0}, cx[4] = {0, 0, 0, 0};
    bool bad[4] = {false, false, false, false};
#pragma unroll
    for (int t = 0; t < kT; t++) {
        const size_t o = (size_t)t * kMD + i4;
        float4 xq = *(const float4*)(g_pre + o);
        float4 xk = *(const float4*)(g_pre + kTMD + o);
        float4 xv = *(const float4*)(g_pre + 2 * kTMD + o);
        __half ob[4];
#pragma unroll
        for (int e = 0; e < 4; e++) {
            mq[e] = mq[e] * 0.9f + (&xq.x)[e];
            mk[e] = mk[e] * 0.9f + (&xk.x)[e];
            mv[e] = mv[e] * 0.9f + (&xv.x)[e];
            bad[e] = bad[e] | (fabsf(mq[e] - 1.0f) < kDelta)
                            | (fabsf(mk[e] - 1.0f) < kDelta)
                            | (fabsf(mv[e] - 1.0f) < kDelta);
            const float sq = (mq[e] >= 1.0f) ? 1.f : 0.f;
            const float sk = (mk[e] >= 1.0f) ? 1.f : 0.f;
            const float sv = (mv[e] >= 1.0f) ? 1.f : 0.f;
            mq[e] -= sq; mk[e] -= sk; mv[e] -= sv;
            cx[e] += sk * sv;
            ob[e] = __float2half_rn(sq * cx[e]);   // exact (0..4)
        }
        *(uint2*)(g_o + o) = *(uint2*)ob;
    }
#pragma unroll
    for (int e = 0; e < 4; e++)
        if (bad[e]) {
            int p = atomicAdd(&g_cnt, 1);
            if (p < kFlagCap) g_flags[p] = (int)(i4 + e);
        }
}

// Exact recompute of flagged elements: 12 independent strict-k-ascending fp32
// fmaf chains fed by float4 loads (bit-identical to reference), LIF redo.
__global__ void fix_flagged(const float* __restrict__ x, const float* __restrict__ Wq,
                            const float* __restrict__ Wk, const float* __restrict__ Wv) {
    const int n = g_cnt < kFlagCap ? g_cnt : kFlagCap;
    for (int j = blockIdx.x * blockDim.x + threadIdx.x; j < n;
         j += gridDim.x * blockDim.x) {
        const int e = g_flags[j];
        const int row = e >> 9, d = e & (kD - 1);
        const float4* wq4 = (const float4*)(Wq + (size_t)d * kD);
        const float4* wk4 = (const float4*)(Wk + (size_t)d * kD);
        const float4* wv4 = (const float4*)(Wv + (size_t)d * kD);
        const float4* xr4[kT];
#pragma unroll
        for (int t = 0; t < kT; t++)
            xr4[t] = (const float4*)(x + ((size_t)t * kM + row) * kD);

        float aq[kT] = {0, 0, 0, 0}, ak[kT] = {0, 0, 0, 0}, av[kT] = {0, 0, 0, 0};
        for (int k4 = 0; k4 < kD / 4; k4++) {     // strict ascending k per chain
            const float4 wqv = wq4[k4], wkv = wk4[k4], wvv = wv4[k4];
#pragma unroll
            for (int t = 0; t < kT; t++) {
                const float4 xv = xr4[t][k4];
                aq[t] = fmaf(xv.x, wqv.x, aq[t]);
                aq[t] = fmaf(xv.y, wqv.y, aq[t]);
                aq[t] = fmaf(xv.z, wqv.z, aq[t]);
                aq[t] = fmaf(xv.w, wqv.w, aq[t]);
                ak[t] = fmaf(xv.x, wkv.x, ak[t]);
                ak[t] = fmaf(xv.y, wkv.y, ak[t]);
                ak[t] = fmaf(xv.z, wkv.z, ak[t]);
                ak[t] = fmaf(xv.w, wkv.w, ak[t]);
                av[t] = fmaf(xv.x, wvv.x, av[t]);
                av[t] = fmaf(xv.y, wvv.y, av[t]);
                av[t] = fmaf(xv.z, wvv.z, av[t]);
                av[t] = fmaf(xv.w, wvv.w, av[t]);
            }
        }

        float mq = 0.f, mk = 0.f, mv = 0.f, cx = 0.f;
#pragma unroll
        for (int t = 0; t < kT; t++) {
            mq = mq * 0.9f + aq[t];
            mk = mk * 0.9f + ak[t];
            mv = mv * 0.9f + av[t];
            const float sq = (mq >= 1.0f) ? 1.f : 0.f;
            const float sk = (mk >= 1.0f) ? 1.f : 0.f;
            const float sv = (mv >= 1.0f) ? 1.f : 0.f;
            mq -= sq; mk -= sk; mv -= sv;
            cx += sk * sv;
            g_o[(size_t)t * kMD + e] = __float2half_rn(sq * cx);
        }
    }
}

// ------------------------------ launcher -----------------------------------
extern "C" void kernel_launch(void* const* d_in, const int* in_sizes, int n_in,
                              void* d_out, int out_size) {
    const float* x   = (const float*)d_in[0];
    const float* Wq  = (const float*)d_in[1];
    const float* Wk  = (const float*)d_in[2];
    const float* Wv  = (const float*)d_in[3];
    const float* Wpj = (const float*)d_in[4];
    const float* bp  = (const float*)d_in[5];
    float* out = (float*)d_out;

    constexpr size_t GEMM_SMEM = (size_t)STAGES * 2 * TILE_B;   // 49152
    cudaFuncSetAttribute(qkv_mma, cudaFuncAttributeMaxDynamicSharedMemorySize, (int)GEMM_SMEM);
    cudaFuncSetAttribute(proj_mma, cudaFuncAttributeMaxDynamicSharedMemorySize, (int)GEMM_SMEM);

    split_w<<<kWEl / 256, 256>>>(Wq, Wk, Wv, Wpj);
    split_x<<<(int)(kTMD / 1024), 256>>>(x);
    qkv_mma<<<6144, 256, GEMM_SMEM>>>();
    lif_fuse<<<(int)(kMD / 1024), 256>>>();
    fix_flagged<<<1024, 128>>>(x, Wq, Wk, Wv);
    proj_mma<<<2048, 256, GEMM_SMEM>>>(bp, out);
}